// round 5
// baseline (speedup 1.0000x reference)
#include <cuda_runtime.h>
#include <cuda_bf16.h>
#include <math.h>
#include <stdint.h>

// Problem constants
#define BTN   128
#define SEQ   256
#define DIM   1024
#define NH    16
#define NKV   4
#define GRP   4
#define HD    64
#define MROWS (BTN*SEQ)      // 32768
#define QKVC  1536
#define GK    1024
#define EPSV  1e-6f
#define SCALEV 0.125f
#define CAPV  50.0f

// ---------------------------------------------------------------------------
// Scratch (device globals)
// ---------------------------------------------------------------------------
__device__ float g_qkv[(size_t)MROWS * QKVC];
__device__ __align__(16) __nv_bfloat16 g_xh[(size_t)MROWS * GK];  // x split; reused as Q tiles
__device__ __align__(16) __nv_bfloat16 g_xl[(size_t)MROWS * GK];
__device__ __align__(16) __nv_bfloat16 g_ah[(size_t)MROWS * GK];  // attn out hi
__device__ __align__(16) __nv_bfloat16 g_al[(size_t)MROWS * GK];
__device__ __align__(16) __nv_bfloat16 g_kh[(size_t)MROWS * 256]; // K tiles (bt,kvh)
__device__ __align__(16) __nv_bfloat16 g_kl[(size_t)MROWS * 256];
__device__ __align__(16) __nv_bfloat16 g_vh[(size_t)MROWS * 256];
__device__ __align__(16) __nv_bfloat16 g_vl[(size_t)MROWS * 256];
__device__ __align__(16) __nv_bfloat16 g_wqkvh[(size_t)QKVC * GK]; // [n][k]
__device__ __align__(16) __nv_bfloat16 g_wqkvl[(size_t)QKVC * GK];
__device__ __align__(16) __nv_bfloat16 g_woh[(size_t)DIM * GK];
__device__ __align__(16) __nv_bfloat16 g_wol[(size_t)DIM * GK];

// ---------------------------------------------------------------------------
// helpers
// ---------------------------------------------------------------------------
__device__ __forceinline__ uint32_t smem_u32(const void* p) {
    uint32_t a;
    asm("{ .reg .u64 t; cvta.to.shared.u64 t, %1; cvt.u32.u64 %0, t; }"
        : "=r"(a) : "l"(p));
    return a;
}
__device__ __forceinline__ void cp16(uint32_t dst, const void* src) {
    asm volatile("cp.async.cg.shared.global [%0], [%1], 16;" :: "r"(dst), "l"(src));
}
__device__ __forceinline__ void ldmx4(uint32_t r[4], uint32_t addr) {
    asm volatile("ldmatrix.sync.aligned.m8n8.x4.shared.b16 {%0,%1,%2,%3}, [%4];"
                 : "=r"(r[0]), "=r"(r[1]), "=r"(r[2]), "=r"(r[3]) : "r"(addr));
}
__device__ __forceinline__ void ldmx4t(uint32_t r[4], uint32_t addr) {
    asm volatile("ldmatrix.sync.aligned.m8n8.x4.trans.shared.b16 {%0,%1,%2,%3}, [%4];"
                 : "=r"(r[0]), "=r"(r[1]), "=r"(r[2]), "=r"(r[3]) : "r"(addr));
}
__device__ __forceinline__ void mma16816(float c[4], const uint32_t a[4],
                                         const uint32_t b[2]) {
    asm volatile("mma.sync.aligned.m16n8k16.row.col.f32.bf16.bf16.f32 "
                 "{%0,%1,%2,%3}, {%4,%5,%6,%7}, {%8,%9}, {%0,%1,%2,%3};"
                 : "+f"(c[0]), "+f"(c[1]), "+f"(c[2]), "+f"(c[3])
                 : "r"(a[0]), "r"(a[1]), "r"(a[2]), "r"(a[3]),
                   "r"(b[0]), "r"(b[1]));
}
__device__ __forceinline__ void split2(float a, float b, uint32_t& H, uint32_t& L) {
    __nv_bfloat16 ah = __float2bfloat16(a), bh = __float2bfloat16(b);
    __nv_bfloat162 hh(ah, bh);
    H = *(uint32_t*)&hh;
    __nv_bfloat162 ll(__float2bfloat16(a - __bfloat162float(ah)),
                      __float2bfloat16(b - __bfloat162float(bh)));
    L = *(uint32_t*)&ll;
}
#define ASW(o) ((o) ^ (((o) >> 3) & 0x70))

// ---------------------------------------------------------------------------
// conversions
// ---------------------------------------------------------------------------
__global__ void cvt_split(const float* __restrict__ in,
                          __nv_bfloat16* __restrict__ h,
                          __nv_bfloat16* __restrict__ l, int n4)
{
    int i = blockIdx.x * blockDim.x + threadIdx.x;
    if (i >= n4) return;
    float4 v = ((const float4*)in)[i];
    uint32_t H0, L0, H1, L1;
    split2(v.x, v.y, H0, L0);
    split2(v.z, v.w, H1, L1);
    ((uint2*)h)[i] = make_uint2(H0, H1);
    ((uint2*)l)[i] = make_uint2(L0, L1);
}

__global__ void xpose_qkv(const float* __restrict__ Wq, const float* __restrict__ Wk,
                          const float* __restrict__ Wv,
                          __nv_bfloat16* __restrict__ th, __nv_bfloat16* __restrict__ tl)
{
    size_t idx = (size_t)blockIdx.x * blockDim.x + threadIdx.x;
    if (idx >= (size_t)QKVC * GK) return;
    int k = (int)(idx & (GK - 1));
    int n = (int)(idx >> 10);
    float v;
    if (n < DIM)            v = Wq[(size_t)k * (NH*HD)  + n];
    else if (n < DIM + 256) v = Wk[(size_t)k * (NKV*HD) + (n - DIM)];
    else                    v = Wv[(size_t)k * (NKV*HD) + (n - DIM - 256)];
    __nv_bfloat16 hv = __float2bfloat16(v);
    th[idx] = hv;
    tl[idx] = __float2bfloat16(v - __bfloat162float(hv));
}

__global__ void xpose_wo(const float* __restrict__ W,
                         __nv_bfloat16* __restrict__ th, __nv_bfloat16* __restrict__ tl)
{
    size_t idx = (size_t)blockIdx.x * blockDim.x + threadIdx.x;
    if (idx >= (size_t)DIM * GK) return;
    int k = (int)(idx & (GK - 1));
    int n = (int)(idx >> 10);
    float v = W[(size_t)k * DIM + n];
    __nv_bfloat16 hv = __float2bfloat16(v);
    th[idx] = hv;
    tl[idx] = __float2bfloat16(v - __bfloat162float(hv));
}

// ---------------------------------------------------------------------------
// HMMA bf16x3 GEMM: 128(m) x 256(n) CTA tile, BK=32, 3-stage, 512 threads.
// ---------------------------------------------------------------------------
#define BK      32
#define NCHUNK  (GK / BK)
#define ROWB    80
#define TA      (128 * ROWB)             // 10240
#define TB      (256 * ROWB)             // 20480
#define OFF_AH  0
#define OFF_AL  TA
#define OFF_BH  (2*TA)
#define OFF_BL  (2*TA + TB)
#define STG     (2*TA + 2*TB)            // 61440
#define SMEM_GEMM (3 * STG + 1024)       // 185344

__device__ __forceinline__ void g_load(uint32_t sbase, int tid,
    const __nv_bfloat16* Ah, const __nv_bfloat16* Al,
    const __nv_bfloat16* Bh, const __nv_bfloat16* Bl, int koff)
{
    const int row = tid >> 2;          // 0..127
    const int c4  = tid & 3;
    const uint32_t doff = (uint32_t)row * ROWB + c4 * 16;
    const size_t soff = (size_t)row * GK + koff + c4 * 8;
    const size_t sstep = (size_t)128 * GK;
    cp16(sbase + OFF_AH + doff, Ah + soff);
    cp16(sbase + OFF_AL + doff, Al + soff);
    cp16(sbase + OFF_BH + doff, Bh + soff);
    cp16(sbase + OFF_BH + doff + TA, Bh + soff + sstep);   // TA = 128*ROWB rows offset
    cp16(sbase + OFF_BL + doff, Bl + soff);
    cp16(sbase + OFF_BL + doff + TA, Bl + soff + sstep);
    asm volatile("cp.async.commit_group;" ::: "memory");
}

__global__ void __launch_bounds__(512, 1)
gemm_mma(const __nv_bfloat16* __restrict__ ah, const __nv_bfloat16* __restrict__ al,
         const __nv_bfloat16* __restrict__ bh, const __nv_bfloat16* __restrict__ bl,
         float* __restrict__ C, int ldc)
{
    extern __shared__ char smem_raw[];
    uint32_t sbr = smem_u32(smem_raw);
    const uint32_t sb = (sbr + 1023) & ~1023u;
    const int tid  = threadIdx.x;
    const int wid  = tid >> 5;
    const int lane = tid & 31;
    const int bm = blockIdx.y * 128;
    const int bn = blockIdx.x * 256;

    const __nv_bfloat16* Ah = ah + (size_t)bm * GK;
    const __nv_bfloat16* Al = al + (size_t)bm * GK;
    const __nv_bfloat16* Bh = bh + (size_t)bn * GK;
    const __nv_bfloat16* Bl = bl + (size_t)bn * GK;

    const int wm = (wid & 3) * 32;        // 4 m positions
    const int wn = (wid >> 2) * 64;       // 4 n positions
    const int ar = lane & 15;
    const int ac = (lane >> 4) * 16;

    float acc[2][8][4];
    #pragma unroll
    for (int i = 0; i < 2; i++)
        #pragma unroll
        for (int j = 0; j < 8; j++)
            #pragma unroll
            for (int e = 0; e < 4; e++) acc[i][j][e] = 0.f;

    g_load(sb,           tid, Ah, Al, Bh, Bl, 0);
    g_load(sb + STG,     tid, Ah, Al, Bh, Bl, BK);

    for (int c = 0; c < NCHUNK; c++) {
        if (c + 1 < NCHUNK)
            asm volatile("cp.async.wait_group 1;" ::: "memory");
        else
            asm volatile("cp.async.wait_group 0;" ::: "memory");
        __syncthreads();
        if (c + 2 < NCHUNK)
            g_load(sb + ((c + 2) % 3) * STG, tid, Ah, Al, Bh, Bl, (c + 2) * BK);

        const uint32_t st = sb + (c % 3) * STG;
        #pragma unroll
        for (int kk = 0; kk < 2; kk++) {
            const int kb = kk * 32;
            uint32_t fAh[2][4], fAl[2][4];
            #pragma unroll
            for (int mt = 0; mt < 2; mt++) {
                uint32_t arow = (uint32_t)(wm + mt * 16 + ar) * ROWB + kb + ac;
                ldmx4(fAh[mt], st + OFF_AH + arow);
                ldmx4(fAl[mt], st + OFF_AL + arow);
            }
            #pragma unroll
            for (int half = 0; half < 2; half++) {
                uint32_t fBh[4][2], fBl[4][2];
                #pragma unroll
                for (int np = 0; np < 2; np++) {
                    uint32_t brow = (uint32_t)(wn + (half * 2 + np) * 16
                                    + (lane & 7) + ((lane >> 4) & 1) * 8) * ROWB
                                    + kb + ((lane >> 3) & 1) * 16;
                    uint32_t t[4];
                    ldmx4(t, st + OFF_BH + brow);
                    fBh[np*2][0] = t[0]; fBh[np*2][1] = t[1];
                    fBh[np*2+1][0] = t[2]; fBh[np*2+1][1] = t[3];
                    ldmx4(t, st + OFF_BL + brow);
                    fBl[np*2][0] = t[0]; fBl[np*2][1] = t[1];
                    fBl[np*2+1][0] = t[2]; fBl[np*2+1][1] = t[3];
                }
                #pragma unroll
                for (int mt = 0; mt < 2; mt++)
                    #pragma unroll
                    for (int j = 0; j < 4; j++) {
                        const int nt = half * 4 + j;
                        mma16816(acc[mt][nt], fAh[mt], fBh[j]);
                        mma16816(acc[mt][nt], fAh[mt], fBl[j]);
                        mma16816(acc[mt][nt], fAl[mt], fBh[j]);
                    }
            }
        }
    }

    const int er = lane >> 2;
    const int ec = (lane & 3) * 2;
    #pragma unroll
    for (int mt = 0; mt < 2; mt++)
        #pragma unroll
        for (int nt = 0; nt < 8; nt++) {
            size_t row0 = (size_t)(bm + wm + mt * 16 + er) * ldc
                        + bn + wn + nt * 8 + ec;
            *(float2*)&C[row0]           = make_float2(acc[mt][nt][0], acc[mt][nt][1]);
            *(float2*)&C[row0 + 8 * ldc] = make_float2(acc[mt][nt][2], acc[mt][nt][3]);
        }
}

// ---------------------------------------------------------------------------
// Attention prep: fold rmsnorms + scales, split to bf16 hi/lo tiles.
//   Q tiles: g_xh/g_xl, tile (bt*16+h): [256 s][64 d]
//   K tiles: g_kh/g_kl, tile (bt*4+kvh); V tiles: g_vh/g_vl
// One thread per 64-elem vector. Units: Q: MROWS*16, K: MROWS*4, V: MROWS*4.
// ---------------------------------------------------------------------------
#define PREP_UNITS (MROWS*16 + MROWS*4 + MROWS*4)   // 786432

__global__ void __launch_bounds__(256)
attn_prep(const float* __restrict__ qw, const float* __restrict__ kw)
{
    int u = blockIdx.x * 256 + threadIdx.x;
    float v[HD];
    const float* src;
    __nv_bfloat16 *dh, *dl;
    size_t dbase;
    bool do_norm;
    float pre = 1.0f;

    if (u < MROWS * 16) {                       // Q
        int row = u >> 4, h = u & 15;
        src = g_qkv + (size_t)row * QKVC + h * HD;
        dbase = ((size_t)((row >> 8) * NH + h) * SEQ + (row & 255)) * HD;
        dh = g_xh; dl = g_xl; do_norm = true;
        #pragma unroll
        for (int d = 0; d < HD; d += 4) {
            float4 a = *(const float4*)(src + d);
            v[d] = a.x; v[d+1] = a.y; v[d+2] = a.z; v[d+3] = a.w;
        }
        float ssq = 0.f;
        #pragma unroll
        for (int d = 0; d < HD; d++) ssq += v[d] * v[d];
        float rq = rsqrtf(ssq * (1.0f / HD) + EPSV) * SCALEV * (2.0f / CAPV);
        #pragma unroll
        for (int d = 0; d < HD; d++)
            v[d] *= rq * __ldg(&qw[d]) * __ldg(&kw[d]);
    } else if (u < MROWS * 20) {                // K
        int u2 = u - MROWS * 16;
        int row = u2 >> 2, kvh = u2 & 3;
        src = g_qkv + (size_t)row * QKVC + DIM + kvh * HD;
        dbase = ((size_t)((row >> 8) * NKV + kvh) * SEQ + (row & 255)) * HD;
        dh = g_kh; dl = g_kl;
        #pragma unroll
        for (int d = 0; d < HD; d += 4) {
            float4 a = *(const float4*)(src + d);
            v[d] = a.x; v[d+1] = a.y; v[d+2] = a.z; v[d+3] = a.w;
        }
        float ssq = 0.f;
        #pragma unroll
        for (int d = 0; d < HD; d++) ssq += v[d] * v[d];
        float rk = rsqrtf(ssq * (1.0f / HD) + EPSV);
        #pragma unroll
        for (int d = 0; d < HD; d++) v[d] *= rk;
    } else {                                    // V
        int u2 = u - MROWS * 20;
        int row = u2 >> 2, kvh = u2 & 3;
        src = g_qkv + (size_t)row * QKVC + DIM + NKV * HD + kvh * HD;
        dbase = ((size_t)((row >> 8) * NKV + kvh) * SEQ + (row & 255)) * HD;
        dh = g_vh; dl = g_vl;
        #pragma unroll
        for (int d = 0; d < HD; d += 4) {
            float4 a = *(const float4*)(src + d);
            v[d] = a.x; v[d+1] = a.y; v[d+2] = a.z; v[d+3] = a.w;
        }
    }

    #pragma unroll
    for (int d = 0; d < HD; d += 8) {
        uint4 H, L;
        split2(v[d+0], v[d+1], H.x, L.x);
        split2(v[d+2], v[d+3], H.y, L.y);
        split2(v[d+4], v[d+5], H.z, L.z);
        split2(v[d+6], v[d+7], H.w, L.w);
        *(uint4*)(dh + dbase + d) = H;
        *(uint4*)(dl + dbase + d) = L;
    }
}

// ---------------------------------------------------------------------------
// Tensor-core attention: block per (bt, h), 256 threads (8 warps).
// Stages pre-split bf16 hi/lo tiles via cp.async (swizzled).
// ---------------------------------------------------------------------------
#define ATT_SMEM (6 * 32768 + 1024)

__global__ void __launch_bounds__(256, 1)
attn_mma()
{
    extern __shared__ char smem_raw[];
    uint32_t sbr = smem_u32(smem_raw);
    const uint32_t sb = (sbr + 1023) & ~1023u;
    const uint32_t sQh = sb, sQl = sb + 32768, sKh = sb + 65536,
                   sKl = sb + 98304, sVh = sb + 131072, sVl = sb + 163840;

    const int h  = blockIdx.x;
    const int bt = blockIdx.y;
    const int kvh = h >> 2;
    const int tid = threadIdx.x;
    const int lane = tid & 31;
    const int wid = tid >> 5;

    // ---- staging via cp.async ----
    {
        const size_t qoff = (size_t)(bt * NH + h) * SEQ * HD;
        const size_t koff = (size_t)(bt * NKV + kvh) * SEQ * HD;
        const __nv_bfloat16* srcs[6] = {
            g_xh + qoff, g_xl + qoff, g_kh + koff, g_kl + koff,
            g_vh + koff, g_vl + koff };
        #pragma unroll
        for (int t = 0; t < 6; t++) {
            const __nv_bfloat16* s = srcs[t];
            const uint32_t dtile = sb + t * 32768;
            #pragma unroll
            for (int i = 0; i < 8; i++) {
                uint32_t q = tid + i * 256;       // 0..2047
                uint32_t row = q >> 3, j = q & 7;
                cp16(dtile + ASW(row * 128 + j * 16), s + row * 64 + j * 8);
            }
        }
        asm volatile("cp.async.commit_group;" ::: "memory");
        asm volatile("cp.async.wait_group 0;" ::: "memory");
    }
    __syncthreads();

    const int qm = wid * 32;
    float acc[2][8][4];
    float rsum[2][2];
    #pragma unroll
    for (int i = 0; i < 2; i++) {
        rsum[i][0] = rsum[i][1] = 0.f;
        #pragma unroll
        for (int j = 0; j < 8; j++)
            #pragma unroll
            for (int e = 0; e < 4; e++) acc[i][j][e] = 0.f;
    }

    for (int kb = 0; kb < 4; kb++) {
        float S[2][8][4];
        #pragma unroll
        for (int i = 0; i < 2; i++)
            #pragma unroll
            for (int j = 0; j < 8; j++)
                #pragma unroll
                for (int e = 0; e < 4; e++) S[i][j][e] = 0.f;

        #pragma unroll
        for (int ks = 0; ks < 4; ks++) {
            uint32_t fQh[2][4], fQl[2][4];
            #pragma unroll
            for (int mt = 0; mt < 2; mt++) {
                uint32_t off = ASW((uint32_t)((qm + mt*16 + (lane & 15)) * 128
                              + ks * 32 + ((lane >> 4) & 1) * 16));
                ldmx4(fQh[mt], sQh + off);
                ldmx4(fQl[mt], sQl + off);
            }
            uint32_t fKh[8][2], fKl[8][2];
            #pragma unroll
            for (int np = 0; np < 4; np++) {
                uint32_t krow = kb*64 + np*16 + (lane & 7) + ((lane >> 4) & 1) * 8;
                uint32_t off = ASW(krow * 128 + ks * 32 + ((lane >> 3) & 1) * 16);
                uint32_t t[4];
                ldmx4(t, sKh + off);
                fKh[2*np][0] = t[0]; fKh[2*np][1] = t[1];
                fKh[2*np+1][0] = t[2]; fKh[2*np+1][1] = t[3];
                ldmx4(t, sKl + off);
                fKl[2*np][0] = t[0]; fKl[2*np][1] = t[1];
                fKl[2*np+1][0] = t[2]; fKl[2*np+1][1] = t[3];
            }
            #pragma unroll
            for (int mt = 0; mt < 2; mt++)
                #pragma unroll
                for (int nt = 0; nt < 8; nt++) {
                    mma16816(S[mt][nt], fQh[mt], fKh[nt]);
                    mma16816(S[mt][nt], fQh[mt], fKl[nt]);
                    mma16816(S[mt][nt], fQl[mt], fKh[nt]);
                }
        }

        uint32_t pAh[2][4][4], pAl[2][4][4];
        #pragma unroll
        for (int mt = 0; mt < 2; mt++) {
            #pragma unroll
            for (int nt = 0; nt < 8; nt++) {
                #pragma unroll
                for (int e = 0; e < 4; e++) {
                    float uu = __expf(S[mt][nt][e]);
                    S[mt][nt][e] = __expf(__fdividef(-2.0f * CAPV, uu + 1.0f));
                }
                rsum[mt][0] += S[mt][nt][0] + S[mt][nt][1];
                rsum[mt][1] += S[mt][nt][2] + S[mt][nt][3];
            }
            #pragma unroll
            for (int kk = 0; kk < 4; kk++) {
                split2(S[mt][2*kk][0],   S[mt][2*kk][1],   pAh[mt][kk][0], pAl[mt][kk][0]);
                split2(S[mt][2*kk][2],   S[mt][2*kk][3],   pAh[mt][kk][1], pAl[mt][kk][1]);
                split2(S[mt][2*kk+1][0], S[mt][2*kk+1][1], pAh[mt][kk][2], pAl[mt][kk][2]);
                split2(S[mt][2*kk+1][2], S[mt][2*kk+1][3], pAh[mt][kk][3], pAl[mt][kk][3]);
            }
        }

        #pragma unroll
        for (int kk = 0; kk < 4; kk++) {
            uint32_t fVh[8][2], fVl[8][2];
            #pragma unroll
            for (int np = 0; np < 4; np++) {
                uint32_t vrow = kb*64 + kk*16 + (lane & 7) + ((lane >> 3) & 1) * 8;
                uint32_t off = ASW(vrow * 128 + (np*16 + ((lane >> 4) & 1) * 8) * 2);
                uint32_t t[4];
                ldmx4t(t, sVh + off);
                fVh[2*np][0] = t[0]; fVh[2*np][1] = t[1];
                fVh[2*np+1][0] = t[2]; fVh[2*np+1][1] = t[3];
                ldmx4t(t, sVl + off);
                fVl[2*np][0] = t[0]; fVl[2*np][1] = t[1];
                fVl[2*np+1][0] = t[2]; fVl[2*np+1][1] = t[3];
            }
            #pragma unroll
            for (int mt = 0; mt < 2; mt++)
                #pragma unroll
                for (int nt = 0; nt < 8; nt++) {
                    mma16816(acc[mt][nt], pAh[mt][kk], fVh[nt]);
                    mma16816(acc[mt][nt], pAh[mt][kk], fVl[nt]);
                    mma16816(acc[mt][nt], pAl[mt][kk], fVh[nt]);
                }
        }
    }

    #pragma unroll
    for (int mt = 0; mt < 2; mt++) {
        rsum[mt][0] += __shfl_xor_sync(0xffffffffu, rsum[mt][0], 1);
        rsum[mt][0] += __shfl_xor_sync(0xffffffffu, rsum[mt][0], 2);
        rsum[mt][1] += __shfl_xor_sync(0xffffffffu, rsum[mt][1], 1);
        rsum[mt][1] += __shfl_xor_sync(0xffffffffu, rsum[mt][1], 2);
    }
    #pragma unroll
    for (int mt = 0; mt < 2; mt++) {
        const float inv0 = 1.0f / rsum[mt][0];
        const float inv1 = 1.0f / rsum[mt][1];
        #pragma unroll
        for (int nt = 0; nt < 8; nt++) {
            int rq_ = qm + mt*16 + (lane >> 2);
            int col = nt*8 + (lane & 3) * 2;
            size_t o0 = (size_t)(bt * SEQ + rq_) * GK + h * HD + col;
            size_t o1 = o0 + (size_t)8 * GK;
            uint32_t H, L;
            split2(acc[mt][nt][0] * inv0, acc[mt][nt][1] * inv0, H, L);
            *(uint32_t*)(g_ah + o0) = H;
            *(uint32_t*)(g_al + o0) = L;
            split2(acc[mt][nt][2] * inv1, acc[mt][nt][3] * inv1, H, L);
            *(uint32_t*)(g_ah + o1) = H;
            *(uint32_t*)(g_al + o1) = L;
        }
    }
}

// ---------------------------------------------------------------------------
// launch
// ---------------------------------------------------------------------------
extern "C" void kernel_launch(void* const* d_in, const int* in_sizes, int n_in,
                              void* d_out, int out_size)
{
    const float* x  = (const float*)d_in[0];
    const float* Wq = (const float*)d_in[1];
    const float* Wk = (const float*)d_in[2];
    const float* Wv = (const float*)d_in[3];
    const float* Wo = (const float*)d_in[4];
    const float* qw = (const float*)d_in[5];
    const float* kw = (const float*)d_in[6];
    float* out = (float*)d_out;

    static float* qkv = nullptr;
    static __nv_bfloat16 *xh, *xl, *aah, *aal, *wqh, *wql, *woh, *wol;
    if (!qkv) {
        cudaGetSymbolAddress((void**)&qkv, g_qkv);
        cudaGetSymbolAddress((void**)&xh,  g_xh);
        cudaGetSymbolAddress((void**)&xl,  g_xl);
        cudaGetSymbolAddress((void**)&aah, g_ah);
        cudaGetSymbolAddress((void**)&aal, g_al);
        cudaGetSymbolAddress((void**)&wqh, g_wqkvh);
        cudaGetSymbolAddress((void**)&wql, g_wqkvl);
        cudaGetSymbolAddress((void**)&woh, g_woh);
        cudaGetSymbolAddress((void**)&wol, g_wol);
        cudaFuncSetAttribute(attn_mma,
                             cudaFuncAttributeMaxDynamicSharedMemorySize, ATT_SMEM);
        cudaFuncSetAttribute(gemm_mma,
                             cudaFuncAttributeMaxDynamicSharedMemorySize, SMEM_GEMM);
    }

    const int n4 = MROWS * GK / 4;
    cvt_split<<<(n4 + 255) / 256, 256>>>(x, xh, xl, n4);
    xpose_qkv<<<(QKVC * GK + 255) / 256, 256>>>(Wq, Wk, Wv, wqh, wql);
    xpose_wo<<<(DIM * GK + 255) / 256, 256>>>(Wo, woh, wol);

    gemm_mma<<<dim3(QKVC / 256, MROWS / 128), 512, SMEM_GEMM>>>(
        xh, xl, wqh, wql, qkv, QKVC);

    attn_prep<<<PREP_UNITS / 256, 256>>>(qw, kw);

    attn_mma<<<dim3(NH, BTN), 256, ATT_SMEM>>>();

    gemm_mma<<<dim3(DIM / 256, MROWS / 128), 512, SMEM_GEMM>>>(
        aah, aal, woh, wol, out, DIM);
}

// round 6
// speedup vs baseline: 1.3617x; 1.3617x over previous
#include <cuda_runtime.h>
#include <cuda_bf16.h>
#include <cuda_fp16.h>
#include <math.h>
#include <stdint.h>

// Problem constants
#define BTN   128
#define SEQ   256
#define DIM   1024
#define NH    16
#define NKV   4
#define GRP   4
#define HD    64
#define MROWS (BTN*SEQ)      // 32768
#define QKVC  1536
#define GK    1024
#define EPSV  1e-6f
#define SCALEV 0.125f
#define CAPV  50.0f

// ---------------------------------------------------------------------------
// Scratch (device globals)
// ---------------------------------------------------------------------------
__device__ float g_qkv[(size_t)MROWS * QKVC];
__device__ __align__(16) __half g_x16[(size_t)MROWS * GK];        // x as fp16
__device__ __align__(16) __half g_a16[(size_t)MROWS * GK];        // attn out fp16
__device__ __align__(16) __half g_w1h[(size_t)QKVC * GK];         // [n][k] hi
__device__ __align__(16) __half g_w1l[(size_t)QKVC * GK];         // [n][k] lo
__device__ __align__(16) __half g_w2h[(size_t)DIM * GK];
__device__ __align__(16) __half g_w2l[(size_t)DIM * GK];
// attention tiles (bf16 hi/lo)
__device__ __align__(16) __nv_bfloat16 g_qth[(size_t)MROWS * GK];
__device__ __align__(16) __nv_bfloat16 g_qtl[(size_t)MROWS * GK];
__device__ __align__(16) __nv_bfloat16 g_kh[(size_t)MROWS * 256];
__device__ __align__(16) __nv_bfloat16 g_kl[(size_t)MROWS * 256];
__device__ __align__(16) __nv_bfloat16 g_vh[(size_t)MROWS * 256];
__device__ __align__(16) __nv_bfloat16 g_vl[(size_t)MROWS * 256];

// ---------------------------------------------------------------------------
// helpers
// ---------------------------------------------------------------------------
__device__ __forceinline__ uint32_t smem_u32(const void* p) {
    uint32_t a;
    asm("{ .reg .u64 t; cvta.to.shared.u64 t, %1; cvt.u32.u64 %0, t; }"
        : "=r"(a) : "l"(p));
    return a;
}
__device__ __forceinline__ void cp16(uint32_t dst, const void* src) {
    asm volatile("cp.async.cg.shared.global [%0], [%1], 16;" :: "r"(dst), "l"(src));
}
__device__ __forceinline__ void ldmx4(uint32_t r[4], uint32_t addr) {
    asm volatile("ldmatrix.sync.aligned.m8n8.x4.shared.b16 {%0,%1,%2,%3}, [%4];"
                 : "=r"(r[0]), "=r"(r[1]), "=r"(r[2]), "=r"(r[3]) : "r"(addr));
}
__device__ __forceinline__ void ldmx4t(uint32_t r[4], uint32_t addr) {
    asm volatile("ldmatrix.sync.aligned.m8n8.x4.trans.shared.b16 {%0,%1,%2,%3}, [%4];"
                 : "=r"(r[0]), "=r"(r[1]), "=r"(r[2]), "=r"(r[3]) : "r"(addr));
}
// bf16 mma (attention)
__device__ __forceinline__ void mma_bf(float c[4], const uint32_t a[4],
                                       const uint32_t b[2]) {
    asm volatile("mma.sync.aligned.m16n8k16.row.col.f32.bf16.bf16.f32 "
                 "{%0,%1,%2,%3}, {%4,%5,%6,%7}, {%8,%9}, {%0,%1,%2,%3};"
                 : "+f"(c[0]), "+f"(c[1]), "+f"(c[2]), "+f"(c[3])
                 : "r"(a[0]), "r"(a[1]), "r"(a[2]), "r"(a[3]),
                   "r"(b[0]), "r"(b[1]));
}
// fp16 mma (GEMMs)
__device__ __forceinline__ void mma_fp(float c[4], const uint32_t a[4],
                                       const uint32_t b[2]) {
    asm volatile("mma.sync.aligned.m16n8k16.row.col.f32.f16.f16.f32 "
                 "{%0,%1,%2,%3}, {%4,%5,%6,%7}, {%8,%9}, {%0,%1,%2,%3};"
                 : "+f"(c[0]), "+f"(c[1]), "+f"(c[2]), "+f"(c[3])
                 : "r"(a[0]), "r"(a[1]), "r"(a[2]), "r"(a[3]),
                   "r"(b[0]), "r"(b[1]));
}
__device__ __forceinline__ void split2(float a, float b, uint32_t& H, uint32_t& L) {
    __nv_bfloat16 ah = __float2bfloat16(a), bh = __float2bfloat16(b);
    __nv_bfloat162 hh(ah, bh);
    H = *(uint32_t*)&hh;
    __nv_bfloat162 ll(__float2bfloat16(a - __bfloat162float(ah)),
                      __float2bfloat16(b - __bfloat162float(bh)));
    L = *(uint32_t*)&ll;
}
#define ASW(o) ((o) ^ (((o) >> 3) & 0x70))

// ---------------------------------------------------------------------------
// conversions
// ---------------------------------------------------------------------------
__global__ void cvt_half(const float* __restrict__ in,
                         __half* __restrict__ out, int n4)
{
    int i = blockIdx.x * blockDim.x + threadIdx.x;
    if (i >= n4) return;
    float4 v = ((const float4*)in)[i];
    __half2* op = (__half2*)out;
    op[2*i]   = __floats2half2_rn(v.x, v.y);
    op[2*i+1] = __floats2half2_rn(v.z, v.w);
}

__global__ void xpose_qkv(const float* __restrict__ Wq, const float* __restrict__ Wk,
                          const float* __restrict__ Wv,
                          __half* __restrict__ th, __half* __restrict__ tl)
{
    size_t idx = (size_t)blockIdx.x * blockDim.x + threadIdx.x;
    if (idx >= (size_t)QKVC * GK) return;
    int k = (int)(idx & (GK - 1));
    int n = (int)(idx >> 10);
    float v;
    if (n < DIM)            v = Wq[(size_t)k * (NH*HD)  + n];
    else if (n < DIM + 256) v = Wk[(size_t)k * (NKV*HD) + (n - DIM)];
    else                    v = Wv[(size_t)k * (NKV*HD) + (n - DIM - 256)];
    __half hv = __float2half_rn(v);
    th[idx] = hv;
    tl[idx] = __float2half_rn(v - __half2float(hv));
}

__global__ void xpose_wo(const float* __restrict__ W,
                         __half* __restrict__ th, __half* __restrict__ tl)
{
    size_t idx = (size_t)blockIdx.x * blockDim.x + threadIdx.x;
    if (idx >= (size_t)DIM * GK) return;
    int k = (int)(idx & (GK - 1));
    int n = (int)(idx >> 10);
    float v = W[(size_t)k * DIM + n];
    __half hv = __float2half_rn(v);
    th[idx] = hv;
    tl[idx] = __float2half_rn(v - __half2float(hv));
}

// ---------------------------------------------------------------------------
// fp16 2-term GEMM: C[m,n] = A[m,:].(Bh[n,:]+Bl[n,:]),  K=1024
// 128x128 CTA tile, BK=32, 3-stage cp.async, 256 threads, 2 CTAs/SM.
// ---------------------------------------------------------------------------
#define BK      32
#define NCHUNK  (GK / BK)
#define ROWB    80
#define TILE_B  (128 * ROWB)          // 10240
#define OFF_A   0
#define OFF_BH  TILE_B
#define OFF_BL  (2*TILE_B)
#define STG     (3*TILE_B)            // 30720
#define SMEM_GEMM (3 * STG + 1024)    // 93184

__device__ __forceinline__ void g_load(uint32_t sbase, int tid,
    const __half* A, const __half* Bh, const __half* Bl, int koff)
{
    #pragma unroll
    for (int it = 0; it < 2; it++) {
        int idx = tid + it * 256;
        int row = idx >> 2;
        int c4  = idx & 3;
        uint32_t dst = sbase + row * ROWB + c4 * 16;
        size_t so = (size_t)row * GK + koff + c4 * 8;
        cp16(dst + OFF_A,  A  + so);
        cp16(dst + OFF_BH, Bh + so);
        cp16(dst + OFF_BL, Bl + so);
    }
    asm volatile("cp.async.commit_group;" ::: "memory");
}

__global__ void __launch_bounds__(256, 2)
gemm_mma(const __half* __restrict__ a, const __half* __restrict__ bh,
         const __half* __restrict__ bl, float* __restrict__ C, int ldc)
{
    extern __shared__ char smem_raw[];
    uint32_t sbr = smem_u32(smem_raw);
    const uint32_t sb = (sbr + 1023) & ~1023u;
    const int tid  = threadIdx.x;
    const int wid  = tid >> 5;
    const int lane = tid & 31;
    const int bm = blockIdx.y * 128;
    const int bn = blockIdx.x * 128;

    const __half* A  = a  + (size_t)bm * GK;
    const __half* Bh = bh + (size_t)bn * GK;
    const __half* Bl = bl + (size_t)bn * GK;

    const int wm = (wid & 3) * 32;
    const int wn = (wid >> 2) * 64;
    const int ar = lane & 15;
    const int ac = (lane >> 4) * 16;

    float acc[2][8][4];
    #pragma unroll
    for (int i = 0; i < 2; i++)
        #pragma unroll
        for (int j = 0; j < 8; j++)
            #pragma unroll
            for (int e = 0; e < 4; e++) acc[i][j][e] = 0.f;

    g_load(sb,           tid, A, Bh, Bl, 0);
    g_load(sb + STG,     tid, A, Bh, Bl, BK);

    for (int c = 0; c < NCHUNK; c++) {
        if (c + 1 < NCHUNK)
            asm volatile("cp.async.wait_group 1;" ::: "memory");
        else
            asm volatile("cp.async.wait_group 0;" ::: "memory");
        __syncthreads();
        if (c + 2 < NCHUNK)
            g_load(sb + ((c + 2) % 3) * STG, tid, A, Bh, Bl, (c + 2) * BK);

        const uint32_t st = sb + (c % 3) * STG;
        #pragma unroll
        for (int kk = 0; kk < 2; kk++) {
            const int kb = kk * 32;
            uint32_t fA[2][4];
            #pragma unroll
            for (int mt = 0; mt < 2; mt++) {
                uint32_t arow = (uint32_t)(wm + mt * 16 + ar) * ROWB + kb + ac;
                ldmx4(fA[mt], st + OFF_A + arow);
            }
            #pragma unroll
            for (int half = 0; half < 2; half++) {
                uint32_t fBh[4][2], fBl[4][2];
                #pragma unroll
                for (int np = 0; np < 2; np++) {
                    uint32_t brow = (uint32_t)(wn + (half * 2 + np) * 16
                                    + (lane & 7) + ((lane >> 4) & 1) * 8) * ROWB
                                    + kb + ((lane >> 3) & 1) * 16;
                    uint32_t t[4];
                    ldmx4(t, st + OFF_BH + brow);
                    fBh[np*2][0] = t[0]; fBh[np*2][1] = t[1];
                    fBh[np*2+1][0] = t[2]; fBh[np*2+1][1] = t[3];
                    ldmx4(t, st + OFF_BL + brow);
                    fBl[np*2][0] = t[0]; fBl[np*2][1] = t[1];
                    fBl[np*2+1][0] = t[2]; fBl[np*2+1][1] = t[3];
                }
                #pragma unroll
                for (int mt = 0; mt < 2; mt++)
                    #pragma unroll
                    for (int j = 0; j < 4; j++) {
                        const int nt = half * 4 + j;
                        mma_fp(acc[mt][nt], fA[mt], fBh[j]);
                        mma_fp(acc[mt][nt], fA[mt], fBl[j]);
                    }
            }
        }
    }

    const int er = lane >> 2;
    const int ec = (lane & 3) * 2;
    #pragma unroll
    for (int mt = 0; mt < 2; mt++)
        #pragma unroll
        for (int nt = 0; nt < 8; nt++) {
            size_t row0 = (size_t)(bm + wm + mt * 16 + er) * ldc
                        + bn + wn + nt * 8 + ec;
            *(float2*)&C[row0]           = make_float2(acc[mt][nt][0], acc[mt][nt][1]);
            *(float2*)&C[row0 + 8 * ldc] = make_float2(acc[mt][nt][2], acc[mt][nt][3]);
        }
}

// ---------------------------------------------------------------------------
// Attention prep: fold rmsnorms + scales, split to bf16 hi/lo tiles.
// ---------------------------------------------------------------------------
#define PREP_UNITS (MROWS*16 + MROWS*4 + MROWS*4)   // 786432

__global__ void __launch_bounds__(256)
attn_prep(const float* __restrict__ qw, const float* __restrict__ kw)
{
    int u = blockIdx.x * 256 + threadIdx.x;
    float v[HD];
    const float* src;
    __nv_bfloat16 *dh, *dl;
    size_t dbase;

    if (u < MROWS * 16) {                       // Q
        int row = u >> 4, h = u & 15;
        src = g_qkv + (size_t)row * QKVC + h * HD;
        dbase = ((size_t)((row >> 8) * NH + h) * SEQ + (row & 255)) * HD;
        dh = g_qth; dl = g_qtl;
        #pragma unroll
        for (int d = 0; d < HD; d += 4) {
            float4 a = *(const float4*)(src + d);
            v[d] = a.x; v[d+1] = a.y; v[d+2] = a.z; v[d+3] = a.w;
        }
        float ssq = 0.f;
        #pragma unroll
        for (int d = 0; d < HD; d++) ssq += v[d] * v[d];
        float rq = rsqrtf(ssq * (1.0f / HD) + EPSV) * SCALEV * (2.0f / CAPV);
        #pragma unroll
        for (int d = 0; d < HD; d++)
            v[d] *= rq * __ldg(&qw[d]) * __ldg(&kw[d]);
    } else if (u < MROWS * 20) {                // K
        int u2 = u - MROWS * 16;
        int row = u2 >> 2, kvh = u2 & 3;
        src = g_qkv + (size_t)row * QKVC + DIM + kvh * HD;
        dbase = ((size_t)((row >> 8) * NKV + kvh) * SEQ + (row & 255)) * HD;
        dh = g_kh; dl = g_kl;
        #pragma unroll
        for (int d = 0; d < HD; d += 4) {
            float4 a = *(const float4*)(src + d);
            v[d] = a.x; v[d+1] = a.y; v[d+2] = a.z; v[d+3] = a.w;
        }
        float ssq = 0.f;
        #pragma unroll
        for (int d = 0; d < HD; d++) ssq += v[d] * v[d];
        float rk = rsqrtf(ssq * (1.0f / HD) + EPSV);
        #pragma unroll
        for (int d = 0; d < HD; d++) v[d] *= rk;
    } else {                                    // V
        int u2 = u - MROWS * 20;
        int row = u2 >> 2, kvh = u2 & 3;
        src = g_qkv + (size_t)row * QKVC + DIM + NKV * HD + kvh * HD;
        dbase = ((size_t)((row >> 8) * NKV + kvh) * SEQ + (row & 255)) * HD;
        dh = g_vh; dl = g_vl;
        #pragma unroll
        for (int d = 0; d < HD; d += 4) {
            float4 a = *(const float4*)(src + d);
            v[d] = a.x; v[d+1] = a.y; v[d+2] = a.z; v[d+3] = a.w;
        }
    }

    #pragma unroll
    for (int d = 0; d < HD; d += 8) {
        uint4 H, L;
        split2(v[d+0], v[d+1], H.x, L.x);
        split2(v[d+2], v[d+3], H.y, L.y);
        split2(v[d+4], v[d+5], H.z, L.z);
        split2(v[d+6], v[d+7], H.w, L.w);
        *(uint4*)(dh + dbase + d) = H;
        *(uint4*)(dl + dbase + d) = L;
    }
}

// ---------------------------------------------------------------------------
// Tensor-core attention: block per (bt, h), 256 threads (8 warps). bf16x3.
// ---------------------------------------------------------------------------
#define ATT_SMEM (6 * 32768 + 1024)

__global__ void __launch_bounds__(256, 1)
attn_mma()
{
    extern __shared__ char smem_raw[];
    uint32_t sbr = smem_u32(smem_raw);
    const uint32_t sb = (sbr + 1023) & ~1023u;
    const uint32_t sQh = sb, sQl = sb + 32768, sKh = sb + 65536,
                   sKl = sb + 98304, sVh = sb + 131072, sVl = sb + 163840;

    const int h  = blockIdx.x;
    const int bt = blockIdx.y;
    const int kvh = h >> 2;
    const int tid = threadIdx.x;
    const int lane = tid & 31;
    const int wid = tid >> 5;

    {
        const size_t qoff = (size_t)(bt * NH + h) * SEQ * HD;
        const size_t koff = (size_t)(bt * NKV + kvh) * SEQ * HD;
        const __nv_bfloat16* srcs[6] = {
            g_qth + qoff, g_qtl + qoff, g_kh + koff, g_kl + koff,
            g_vh + koff, g_vl + koff };
        #pragma unroll
        for (int t = 0; t < 6; t++) {
            const __nv_bfloat16* s = srcs[t];
            const uint32_t dtile = sb + t * 32768;
            #pragma unroll
            for (int i = 0; i < 8; i++) {
                uint32_t q = tid + i * 256;
                uint32_t row = q >> 3, j = q & 7;
                cp16(dtile + ASW(row * 128 + j * 16), s + row * 64 + j * 8);
            }
        }
        asm volatile("cp.async.commit_group;" ::: "memory");
        asm volatile("cp.async.wait_group 0;" ::: "memory");
    }
    __syncthreads();

    const int qm = wid * 32;
    float acc[2][8][4];
    float rsum[2][2];
    #pragma unroll
    for (int i = 0; i < 2; i++) {
        rsum[i][0] = rsum[i][1] = 0.f;
        #pragma unroll
        for (int j = 0; j < 8; j++)
            #pragma unroll
            for (int e = 0; e < 4; e++) acc[i][j][e] = 0.f;
    }

    for (int kb = 0; kb < 4; kb++) {
        float S[2][8][4];
        #pragma unroll
        for (int i = 0; i < 2; i++)
            #pragma unroll
            for (int j = 0; j < 8; j++)
                #pragma unroll
                for (int e = 0; e < 4; e++) S[i][j][e] = 0.f;

        #pragma unroll
        for (int ks = 0; ks < 4; ks++) {
            uint32_t fQh[2][4], fQl[2][4];
            #pragma unroll
            for (int mt = 0; mt < 2; mt++) {
                uint32_t off = ASW((uint32_t)((qm + mt*16 + (lane & 15)) * 128
                              + ks * 32 + ((lane >> 4) & 1) * 16));
                ldmx4(fQh[mt], sQh + off);
                ldmx4(fQl[mt], sQl + off);
            }
            uint32_t fKh[8][2], fKl[8][2];
            #pragma unroll
            for (int np = 0; np < 4; np++) {
                uint32_t krow = kb*64 + np*16 + (lane & 7) + ((lane >> 4) & 1) * 8;
                uint32_t off = ASW(krow * 128 + ks * 32 + ((lane >> 3) & 1) * 16);
                uint32_t t[4];
                ldmx4(t, sKh + off);
                fKh[2*np][0] = t[0]; fKh[2*np][1] = t[1];
                fKh[2*np+1][0] = t[2]; fKh[2*np+1][1] = t[3];
                ldmx4(t, sKl + off);
                fKl[2*np][0] = t[0]; fKl[2*np][1] = t[1];
                fKl[2*np+1][0] = t[2]; fKl[2*np+1][1] = t[3];
            }
            #pragma unroll
            for (int mt = 0; mt < 2; mt++)
                #pragma unroll
                for (int nt = 0; nt < 8; nt++) {
                    mma_bf(S[mt][nt], fQh[mt], fKh[nt]);
                    mma_bf(S[mt][nt], fQh[mt], fKl[nt]);
                    mma_bf(S[mt][nt], fQl[mt], fKh[nt]);
                }
        }

        uint32_t pAh[2][4][4], pAl[2][4][4];
        #pragma unroll
        for (int mt = 0; mt < 2; mt++) {
            #pragma unroll
            for (int nt = 0; nt < 8; nt++) {
                #pragma unroll
                for (int e = 0; e < 4; e++) {
                    float uu = __expf(S[mt][nt][e]);
                    S[mt][nt][e] = __expf(__fdividef(-2.0f * CAPV, uu + 1.0f));
                }
                rsum[mt][0] += S[mt][nt][0] + S[mt][nt][1];
                rsum[mt][1] += S[mt][nt][2] + S[mt][nt][3];
            }
            #pragma unroll
            for (int kk = 0; kk < 4; kk++) {
                split2(S[mt][2*kk][0],   S[mt][2*kk][1],   pAh[mt][kk][0], pAl[mt][kk][0]);
                split2(S[mt][2*kk][2],   S[mt][2*kk][3],   pAh[mt][kk][1], pAl[mt][kk][1]);
                split2(S[mt][2*kk+1][0], S[mt][2*kk+1][1], pAh[mt][kk][2], pAl[mt][kk][2]);
                split2(S[mt][2*kk+1][2], S[mt][2*kk+1][3], pAh[mt][kk][3], pAl[mt][kk][3]);
            }
        }

        #pragma unroll
        for (int kk = 0; kk < 4; kk++) {
            uint32_t fVh[8][2], fVl[8][2];
            #pragma unroll
            for (int np = 0; np < 4; np++) {
                uint32_t vrow = kb*64 + kk*16 + (lane & 7) + ((lane >> 3) & 1) * 8;
                uint32_t off = ASW(vrow * 128 + (np*16 + ((lane >> 4) & 1) * 8) * 2);
                uint32_t t[4];
                ldmx4t(t, sVh + off);
                fVh[2*np][0] = t[0]; fVh[2*np][1] = t[1];
                fVh[2*np+1][0] = t[2]; fVh[2*np+1][1] = t[3];
                ldmx4t(t, sVl + off);
                fVl[2*np][0] = t[0]; fVl[2*np][1] = t[1];
                fVl[2*np+1][0] = t[2]; fVl[2*np+1][1] = t[3];
            }
            #pragma unroll
            for (int mt = 0; mt < 2; mt++)
                #pragma unroll
                for (int nt = 0; nt < 8; nt++) {
                    mma_bf(acc[mt][nt], pAh[mt][kk], fVh[nt]);
                    mma_bf(acc[mt][nt], pAh[mt][kk], fVl[nt]);
                    mma_bf(acc[mt][nt], pAl[mt][kk], fVh[nt]);
                }
        }
    }

    #pragma unroll
    for (int mt = 0; mt < 2; mt++) {
        rsum[mt][0] += __shfl_xor_sync(0xffffffffu, rsum[mt][0], 1);
        rsum[mt][0] += __shfl_xor_sync(0xffffffffu, rsum[mt][0], 2);
        rsum[mt][1] += __shfl_xor_sync(0xffffffffu, rsum[mt][1], 1);
        rsum[mt][1] += __shfl_xor_sync(0xffffffffu, rsum[mt][1], 2);
    }
    #pragma unroll
    for (int mt = 0; mt < 2; mt++) {
        const float inv0 = 1.0f / rsum[mt][0];
        const float inv1 = 1.0f / rsum[mt][1];
        #pragma unroll
        for (int nt = 0; nt < 8; nt++) {
            int rq_ = qm + mt*16 + (lane >> 2);
            int col = nt*8 + (lane & 3) * 2;
            size_t o0 = (size_t)(bt * SEQ + rq_) * GK + h * HD + col;
            size_t o1 = o0 + (size_t)8 * GK;
            *(__half2*)(g_a16 + o0) =
                __floats2half2_rn(acc[mt][nt][0] * inv0, acc[mt][nt][1] * inv0);
            *(__half2*)(g_a16 + o1) =
                __floats2half2_rn(acc[mt][nt][2] * inv1, acc[mt][nt][3] * inv1);
        }
    }
}

// ---------------------------------------------------------------------------
// launch
// ---------------------------------------------------------------------------
extern "C" void kernel_launch(void* const* d_in, const int* in_sizes, int n_in,
                              void* d_out, int out_size)
{
    const float* x  = (const float*)d_in[0];
    const float* Wq = (const float*)d_in[1];
    const float* Wk = (const float*)d_in[2];
    const float* Wv = (const float*)d_in[3];
    const float* Wo = (const float*)d_in[4];
    const float* qw = (const float*)d_in[5];
    const float* kw = (const float*)d_in[6];
    float* out = (float*)d_out;

    static float* qkv = nullptr;
    static __half *x16, *a16, *w1h, *w1l, *w2h, *w2l;
    if (!qkv) {
        cudaGetSymbolAddress((void**)&qkv, g_qkv);
        cudaGetSymbolAddress((void**)&x16, g_x16);
        cudaGetSymbolAddress((void**)&a16, g_a16);
        cudaGetSymbolAddress((void**)&w1h, g_w1h);
        cudaGetSymbolAddress((void**)&w1l, g_w1l);
        cudaGetSymbolAddress((void**)&w2h, g_w2h);
        cudaGetSymbolAddress((void**)&w2l, g_w2l);
        cudaFuncSetAttribute(attn_mma,
                             cudaFuncAttributeMaxDynamicSharedMemorySize, ATT_SMEM);
        cudaFuncSetAttribute(gemm_mma,
                             cudaFuncAttributeMaxDynamicSharedMemorySize, SMEM_GEMM);
    }

    const int n4 = MROWS * GK / 4;
    cvt_half<<<(n4 + 255) / 256, 256>>>(x, x16, n4);
    xpose_qkv<<<(QKVC * GK + 255) / 256, 256>>>(Wq, Wk, Wv, w1h, w1l);
    xpose_wo<<<(DIM * GK + 255) / 256, 256>>>(Wo, w2h, w2l);

    gemm_mma<<<dim3(QKVC / 128, MROWS / 128), 256, SMEM_GEMM>>>(
        x16, w1h, w1l, qkv, QKVC);

    attn_prep<<<PREP_UNITS / 256, 256>>>(qw, kw);

    attn_mma<<<dim3(NH, BTN), 256, ATT_SMEM>>>();

    gemm_mma<<<dim3(DIM / 128, MROWS / 128), 256, SMEM_GEMM>>>(
        a16, w2h, w2l, out, DIM);
}

// round 7
// speedup vs baseline: 1.4509x; 1.0655x over previous
#include <cuda_runtime.h>
#include <cuda_bf16.h>
#include <cuda_fp16.h>
#include <math.h>
#include <stdint.h>

// Problem constants
#define BTN   128
#define SEQ   256
#define DIM   1024
#define NH    16
#define NKV   4
#define GRP   4
#define HD    64
#define MROWS (BTN*SEQ)      // 32768
#define QKVC  1536
#define GK    1024
#define EPSV  1e-6f
#define SCALEV 0.125f
#define CAPV  50.0f

// ---------------------------------------------------------------------------
// Scratch (device globals)
// ---------------------------------------------------------------------------
__device__ __align__(16) __half g_x16[(size_t)MROWS * GK];        // x as fp16
__device__ __align__(16) __half g_a16[(size_t)MROWS * GK];        // attn out fp16
__device__ __align__(16) __half g_w1h[(size_t)QKVC * GK];         // [n][k] hi
__device__ __align__(16) __half g_w1l[(size_t)QKVC * GK];         // [n][k] lo
__device__ __align__(16) __half g_w2h[(size_t)DIM * GK];
__device__ __align__(16) __half g_w2l[(size_t)DIM * GK];
// attention tiles (bf16 hi/lo)
__device__ __align__(16) __nv_bfloat16 g_qth[(size_t)MROWS * GK];
__device__ __align__(16) __nv_bfloat16 g_qtl[(size_t)MROWS * GK];
__device__ __align__(16) __nv_bfloat16 g_kh[(size_t)MROWS * 256];
__device__ __align__(16) __nv_bfloat16 g_kl[(size_t)MROWS * 256];
__device__ __align__(16) __nv_bfloat16 g_vh[(size_t)MROWS * 256];
__device__ __align__(16) __nv_bfloat16 g_vl[(size_t)MROWS * 256];

// ---------------------------------------------------------------------------
// helpers
// ---------------------------------------------------------------------------
__device__ __forceinline__ uint32_t smem_u32(const void* p) {
    uint32_t a;
    asm("{ .reg .u64 t; cvta.to.shared.u64 t, %1; cvt.u32.u64 %0, t; }"
        : "=r"(a) : "l"(p));
    return a;
}
__device__ __forceinline__ void cp16(uint32_t dst, const void* src) {
    asm volatile("cp.async.cg.shared.global [%0], [%1], 16;" :: "r"(dst), "l"(src));
}
__device__ __forceinline__ void ldmx4(uint32_t r[4], uint32_t addr) {
    asm volatile("ldmatrix.sync.aligned.m8n8.x4.shared.b16 {%0,%1,%2,%3}, [%4];"
                 : "=r"(r[0]), "=r"(r[1]), "=r"(r[2]), "=r"(r[3]) : "r"(addr));
}
__device__ __forceinline__ void ldmx4t(uint32_t r[4], uint32_t addr) {
    asm volatile("ldmatrix.sync.aligned.m8n8.x4.trans.shared.b16 {%0,%1,%2,%3}, [%4];"
                 : "=r"(r[0]), "=r"(r[1]), "=r"(r[2]), "=r"(r[3]) : "r"(addr));
}
__device__ __forceinline__ void mma_bf(float c[4], const uint32_t a[4],
                                       const uint32_t b[2]) {
    asm volatile("mma.sync.aligned.m16n8k16.row.col.f32.bf16.bf16.f32 "
                 "{%0,%1,%2,%3}, {%4,%5,%6,%7}, {%8,%9}, {%0,%1,%2,%3};"
                 : "+f"(c[0]), "+f"(c[1]), "+f"(c[2]), "+f"(c[3])
                 : "r"(a[0]), "r"(a[1]), "r"(a[2]), "r"(a[3]),
                   "r"(b[0]), "r"(b[1]));
}
__device__ __forceinline__ void mma_fp(float c[4], const uint32_t a[4],
                                       const uint32_t b[2]) {
    asm volatile("mma.sync.aligned.m16n8k16.row.col.f32.f16.f16.f32 "
                 "{%0,%1,%2,%3}, {%4,%5,%6,%7}, {%8,%9}, {%0,%1,%2,%3};"
                 : "+f"(c[0]), "+f"(c[1]), "+f"(c[2]), "+f"(c[3])
                 : "r"(a[0]), "r"(a[1]), "r"(a[2]), "r"(a[3]),
                   "r"(b[0]), "r"(b[1]));
}
__device__ __forceinline__ void split2(float a, float b, uint32_t& H, uint32_t& L) {
    __nv_bfloat16 ah = __float2bfloat16(a), bh = __float2bfloat16(b);
    __nv_bfloat162 hh(ah, bh);
    H = *(uint32_t*)&hh;
    __nv_bfloat162 ll(__float2bfloat16(a - __bfloat162float(ah)),
                      __float2bfloat16(b - __bfloat162float(bh)));
    L = *(uint32_t*)&ll;
}
#define ASW(o) ((o) ^ (((o) >> 3) & 0x70))

// ---------------------------------------------------------------------------
// conversions
// ---------------------------------------------------------------------------
__global__ void cvt_half(const float* __restrict__ in,
                         __half* __restrict__ out, int n4)
{
    int i = blockIdx.x * blockDim.x + threadIdx.x;
    if (i >= n4) return;
    float4 v = ((const float4*)in)[i];
    __half2* op = (__half2*)out;
    op[2*i]   = __floats2half2_rn(v.x, v.y);
    op[2*i+1] = __floats2half2_rn(v.z, v.w);
}

__global__ void xpose_qkv(const float* __restrict__ Wq, const float* __restrict__ Wk,
                          const float* __restrict__ Wv,
                          __half* __restrict__ th, __half* __restrict__ tl)
{
    size_t idx = (size_t)blockIdx.x * blockDim.x + threadIdx.x;
    if (idx >= (size_t)QKVC * GK) return;
    int k = (int)(idx & (GK - 1));
    int n = (int)(idx >> 10);
    float v;
    if (n < DIM)            v = Wq[(size_t)k * (NH*HD)  + n];
    else if (n < DIM + 256) v = Wk[(size_t)k * (NKV*HD) + (n - DIM)];
    else                    v = Wv[(size_t)k * (NKV*HD) + (n - DIM - 256)];
    __half hv = __float2half_rn(v);
    th[idx] = hv;
    tl[idx] = __float2half_rn(v - __half2float(hv));
}

__global__ void xpose_wo(const float* __restrict__ W,
                         __half* __restrict__ th, __half* __restrict__ tl)
{
    size_t idx = (size_t)blockIdx.x * blockDim.x + threadIdx.x;
    if (idx >= (size_t)DIM * GK) return;
    int k = (int)(idx & (GK - 1));
    int n = (int)(idx >> 10);
    float v = W[(size_t)k * DIM + n];
    __half hv = __float2half_rn(v);
    th[idx] = hv;
    tl[idx] = __float2half_rn(v - __half2float(hv));
}

// ---------------------------------------------------------------------------
// fp16 2-term GEMM: C[m,n] = A[m,:].(Bh[n,:]+Bl[n,:]),  K=1024
// 128x128 CTA tile, 4 warps (64x64 warp tiles), BK=32, 3-stage, 2 CTAs/SM.
// EPI=0: plain fp32 store.  EPI=1: QKV epilogue (rmsnorm fold + bf16 split
// into attention tile layout).
// ---------------------------------------------------------------------------
#define BK      32
#define NCHUNK  (GK / BK)
#define ROWB    80
#define TILE_B  (128 * ROWB)          // 10240
#define OFF_A   0
#define OFF_BH  TILE_B
#define OFF_BL  (2*TILE_B)
#define STG     (3*TILE_B)            // 30720
#define SMEM_GEMM (3 * STG + 1024)    // 93184

__device__ __forceinline__ void g_load(uint32_t sbase, int tid,
    const __half* A, const __half* Bh, const __half* Bl, int koff)
{
    #pragma unroll
    for (int it = 0; it < 4; it++) {
        int idx = tid + it * 128;
        int row = idx >> 2;
        int c4  = idx & 3;
        uint32_t dst = sbase + row * ROWB + c4 * 16;
        size_t so = (size_t)row * GK + koff + c4 * 8;
        cp16(dst + OFF_A,  A  + so);
        cp16(dst + OFF_BH, Bh + so);
        cp16(dst + OFF_BL, Bl + so);
    }
    asm volatile("cp.async.commit_group;" ::: "memory");
}

template<int EPI>
__global__ void __launch_bounds__(128, 2)
gemm_mma(const __half* __restrict__ a, const __half* __restrict__ bh,
         const __half* __restrict__ bl, float* __restrict__ C, int ldc,
         const float* __restrict__ qw, const float* __restrict__ kw)
{
    extern __shared__ char smem_raw[];
    uint32_t sbr = smem_u32(smem_raw);
    const uint32_t sb = (sbr + 1023) & ~1023u;
    const int tid  = threadIdx.x;
    const int wid  = tid >> 5;
    const int lane = tid & 31;
    const int bm = blockIdx.y * 128;
    const int bn = blockIdx.x * 128;

    const __half* A  = a  + (size_t)bm * GK;
    const __half* Bh = bh + (size_t)bn * GK;
    const __half* Bl = bl + (size_t)bn * GK;

    const int wm = (wid & 1) * 64;
    const int wn = (wid >> 1) * 64;
    const int ar = lane & 15;
    const int ac = (lane >> 4) * 16;

    float acc[4][8][4];
    #pragma unroll
    for (int i = 0; i < 4; i++)
        #pragma unroll
        for (int j = 0; j < 8; j++)
            #pragma unroll
            for (int e = 0; e < 4; e++) acc[i][j][e] = 0.f;

    g_load(sb,       tid, A, Bh, Bl, 0);
    g_load(sb + STG, tid, A, Bh, Bl, BK);

    for (int c = 0; c < NCHUNK; c++) {
        if (c + 1 < NCHUNK)
            asm volatile("cp.async.wait_group 1;" ::: "memory");
        else
            asm volatile("cp.async.wait_group 0;" ::: "memory");
        __syncthreads();
        if (c + 2 < NCHUNK)
            g_load(sb + ((c + 2) % 3) * STG, tid, A, Bh, Bl, (c + 2) * BK);

        const uint32_t st = sb + (c % 3) * STG;
        #pragma unroll
        for (int kk = 0; kk < 2; kk++) {
            const int kb = kk * 32;
            uint32_t fA[4][4];
            #pragma unroll
            for (int mt = 0; mt < 4; mt++) {
                uint32_t arow = (uint32_t)(wm + mt * 16 + ar) * ROWB + kb + ac;
                ldmx4(fA[mt], st + OFF_A + arow);
            }
            uint32_t fBh[8][2], fBl[8][2];
            #pragma unroll
            for (int g = 0; g < 4; g++) {
                uint32_t brow = (uint32_t)(wn + g * 16
                                + (lane & 7) + ((lane >> 4) & 1) * 8) * ROWB
                                + kb + ((lane >> 3) & 1) * 16;
                uint32_t t[4];
                ldmx4(t, st + OFF_BH + brow);
                fBh[2*g][0] = t[0]; fBh[2*g][1] = t[1];
                fBh[2*g+1][0] = t[2]; fBh[2*g+1][1] = t[3];
                ldmx4(t, st + OFF_BL + brow);
                fBl[2*g][0] = t[0]; fBl[2*g][1] = t[1];
                fBl[2*g+1][0] = t[2]; fBl[2*g+1][1] = t[3];
            }
            #pragma unroll
            for (int mt = 0; mt < 4; mt++)
                #pragma unroll
                for (int nt = 0; nt < 8; nt++) {
                    mma_fp(acc[mt][nt], fA[mt], fBh[nt]);
                    mma_fp(acc[mt][nt], fA[mt], fBl[nt]);
                }
        }
    }

    const int er = lane >> 2;
    const int ec = (lane & 3) * 2;

    if (EPI == 0) {
        #pragma unroll
        for (int mt = 0; mt < 4; mt++)
            #pragma unroll
            for (int nt = 0; nt < 8; nt++) {
                size_t row0 = (size_t)(bm + wm + mt * 16 + er) * ldc
                            + bn + wn + nt * 8 + ec;
                *(float2*)&C[row0]           = make_float2(acc[mt][nt][0], acc[mt][nt][1]);
                *(float2*)&C[row0 + 8 * ldc] = make_float2(acc[mt][nt][2], acc[mt][nt][3]);
            }
        return;
    }

    // ---- EPI == 1: QKV epilogue with fused rmsnorm + bf16 hi/lo split ----
    const int gn = bn + wn;            // multiple of 64; head-aligned
    float wqk[16];
    if (gn < DIM) {
        #pragma unroll
        for (int nt = 0; nt < 8; nt++) {
            int col = nt * 8 + ec;
            wqk[2*nt]   = __ldg(&qw[col])   * __ldg(&kw[col]);
            wqk[2*nt+1] = __ldg(&qw[col+1]) * __ldg(&kw[col+1]);
        }
    }

    #pragma unroll
    for (int mt = 0; mt < 4; mt++) {
        #pragma unroll
        for (int hf = 0; hf < 2; hf++) {
            const int grow = bm + wm + mt * 16 + er + hf * 8;
            const int bt = grow >> 8;
            const int s  = grow & 255;
            float v[16];
            #pragma unroll
            for (int nt = 0; nt < 8; nt++) {
                v[2*nt]   = acc[mt][nt][hf*2];
                v[2*nt+1] = acc[mt][nt][hf*2+1];
            }
            __nv_bfloat16 *dh, *dl;
            size_t dbase;
            if (gn < DIM) {                    // Q: rmsnorm + qw*kw + scales
                float ssq = 0.f;
                #pragma unroll
                for (int j = 0; j < 16; j++) ssq += v[j] * v[j];
                ssq += __shfl_xor_sync(0xffffffffu, ssq, 1);
                ssq += __shfl_xor_sync(0xffffffffu, ssq, 2);
                float r = rsqrtf(ssq * (1.0f / HD) + EPSV) * (SCALEV * 2.0f / CAPV);
                #pragma unroll
                for (int j = 0; j < 16; j++) v[j] *= r * wqk[j];
                int h = gn >> 6;
                dh = g_qth; dl = g_qtl;
                dbase = ((size_t)(bt * NH + h) * SEQ + s) * HD;
            } else if (gn < DIM + 256) {       // K: rmsnorm only
                float ssq = 0.f;
                #pragma unroll
                for (int j = 0; j < 16; j++) ssq += v[j] * v[j];
                ssq += __shfl_xor_sync(0xffffffffu, ssq, 1);
                ssq += __shfl_xor_sync(0xffffffffu, ssq, 2);
                float r = rsqrtf(ssq * (1.0f / HD) + EPSV);
                #pragma unroll
                for (int j = 0; j < 16; j++) v[j] *= r;
                int kvh = (gn - DIM) >> 6;
                dh = g_kh; dl = g_kl;
                dbase = ((size_t)(bt * NKV + kvh) * SEQ + s) * HD;
            } else {                            // V: plain
                int kvh = (gn - DIM - 256) >> 6;
                dh = g_vh; dl = g_vl;
                dbase = ((size_t)(bt * NKV + kvh) * SEQ + s) * HD;
            }
            #pragma unroll
            for (int nt = 0; nt < 8; nt++) {
                uint32_t H, L;
                split2(v[2*nt], v[2*nt+1], H, L);
                *(uint32_t*)(dh + dbase + nt * 8 + ec) = H;
                *(uint32_t*)(dl + dbase + nt * 8 + ec) = L;
            }
        }
    }
}

// ---------------------------------------------------------------------------
// Tensor-core attention: block per (bt, h), 256 threads (8 warps). bf16x3.
// ---------------------------------------------------------------------------
#define ATT_SMEM (6 * 32768 + 1024)

__global__ void __launch_bounds__(256, 1)
attn_mma()
{
    extern __shared__ char smem_raw[];
    uint32_t sbr = smem_u32(smem_raw);
    const uint32_t sb = (sbr + 1023) & ~1023u;
    const uint32_t sQh = sb, sQl = sb + 32768, sKh = sb + 65536,
                   sKl = sb + 98304, sVh = sb + 131072, sVl = sb + 163840;

    const int h  = blockIdx.x;
    const int bt = blockIdx.y;
    const int kvh = h >> 2;
    const int tid = threadIdx.x;
    const int lane = tid & 31;
    const int wid = tid >> 5;

    {
        const size_t qoff = (size_t)(bt * NH + h) * SEQ * HD;
        const size_t koff = (size_t)(bt * NKV + kvh) * SEQ * HD;
        const __nv_bfloat16* srcs[6] = {
            g_qth + qoff, g_qtl + qoff, g_kh + koff, g_kl + koff,
            g_vh + koff, g_vl + koff };
        #pragma unroll
        for (int t = 0; t < 6; t++) {
            const __nv_bfloat16* s = srcs[t];
            const uint32_t dtile = sb + t * 32768;
            #pragma unroll
            for (int i = 0; i < 8; i++) {
                uint32_t q = tid + i * 256;
                uint32_t row = q >> 3, j = q & 7;
                cp16(dtile + ASW(row * 128 + j * 16), s + row * 64 + j * 8);
            }
        }
        asm volatile("cp.async.commit_group;" ::: "memory");
        asm volatile("cp.async.wait_group 0;" ::: "memory");
    }
    __syncthreads();

    const int qm = wid * 32;
    float acc[2][8][4];
    float rsum[2][2];
    #pragma unroll
    for (int i = 0; i < 2; i++) {
        rsum[i][0] = rsum[i][1] = 0.f;
        #pragma unroll
        for (int j = 0; j < 8; j++)
            #pragma unroll
            for (int e = 0; e < 4; e++) acc[i][j][e] = 0.f;
    }

    for (int kb = 0; kb < 4; kb++) {
        float S[2][8][4];
        #pragma unroll
        for (int i = 0; i < 2; i++)
            #pragma unroll
            for (int j = 0; j < 8; j++)
                #pragma unroll
                for (int e = 0; e < 4; e++) S[i][j][e] = 0.f;

        #pragma unroll
        for (int ks = 0; ks < 4; ks++) {
            uint32_t fQh[2][4], fQl[2][4];
            #pragma unroll
            for (int mt = 0; mt < 2; mt++) {
                uint32_t off = ASW((uint32_t)((qm + mt*16 + (lane & 15)) * 128
                              + ks * 32 + ((lane >> 4) & 1) * 16));
                ldmx4(fQh[mt], sQh + off);
                ldmx4(fQl[mt], sQl + off);
            }
            uint32_t fKh[8][2], fKl[8][2];
            #pragma unroll
            for (int np = 0; np < 4; np++) {
                uint32_t krow = kb*64 + np*16 + (lane & 7) + ((lane >> 4) & 1) * 8;
                uint32_t off = ASW(krow * 128 + ks * 32 + ((lane >> 3) & 1) * 16);
                uint32_t t[4];
                ldmx4(t, sKh + off);
                fKh[2*np][0] = t[0]; fKh[2*np][1] = t[1];
                fKh[2*np+1][0] = t[2]; fKh[2*np+1][1] = t[3];
                ldmx4(t, sKl + off);
                fKl[2*np][0] = t[0]; fKl[2*np][1] = t[1];
                fKl[2*np+1][0] = t[2]; fKl[2*np+1][1] = t[3];
            }
            #pragma unroll
            for (int mt = 0; mt < 2; mt++)
                #pragma unroll
                for (int nt = 0; nt < 8; nt++) {
                    mma_bf(S[mt][nt], fQh[mt], fKh[nt]);
                    mma_bf(S[mt][nt], fQh[mt], fKl[nt]);
                    mma_bf(S[mt][nt], fQl[mt], fKh[nt]);
                }
        }

        uint32_t pAh[2][4][4], pAl[2][4][4];
        #pragma unroll
        for (int mt = 0; mt < 2; mt++) {
            #pragma unroll
            for (int nt = 0; nt < 8; nt++) {
                #pragma unroll
                for (int e = 0; e < 4; e++) {
                    float uu = __expf(S[mt][nt][e]);
                    S[mt][nt][e] = __expf(__fdividef(-2.0f * CAPV, uu + 1.0f));
                }
                rsum[mt][0] += S[mt][nt][0] + S[mt][nt][1];
                rsum[mt][1] += S[mt][nt][2] + S[mt][nt][3];
            }
            #pragma unroll
            for (int kk = 0; kk < 4; kk++) {
                split2(S[mt][2*kk][0],   S[mt][2*kk][1],   pAh[mt][kk][0], pAl[mt][kk][0]);
                split2(S[mt][2*kk][2],   S[mt][2*kk][3],   pAh[mt][kk][1], pAl[mt][kk][1]);
                split2(S[mt][2*kk+1][0], S[mt][2*kk+1][1], pAh[mt][kk][2], pAl[mt][kk][2]);
                split2(S[mt][2*kk+1][2], S[mt][2*kk+1][3], pAh[mt][kk][3], pAl[mt][kk][3]);
            }
        }

        #pragma unroll
        for (int kk = 0; kk < 4; kk++) {
            uint32_t fVh[8][2], fVl[8][2];
            #pragma unroll
            for (int np = 0; np < 4; np++) {
                uint32_t vrow = kb*64 + kk*16 + (lane & 7) + ((lane >> 3) & 1) * 8;
                uint32_t off = ASW(vrow * 128 + (np*16 + ((lane >> 4) & 1) * 8) * 2);
                uint32_t t[4];
                ldmx4t(t, sVh + off);
                fVh[2*np][0] = t[0]; fVh[2*np][1] = t[1];
                fVh[2*np+1][0] = t[2]; fVh[2*np+1][1] = t[3];
                ldmx4t(t, sVl + off);
                fVl[2*np][0] = t[0]; fVl[2*np][1] = t[1];
                fVl[2*np+1][0] = t[2]; fVl[2*np+1][1] = t[3];
            }
            #pragma unroll
            for (int mt = 0; mt < 2; mt++)
                #pragma unroll
                for (int nt = 0; nt < 8; nt++) {
                    mma_bf(acc[mt][nt], pAh[mt][kk], fVh[nt]);
                    mma_bf(acc[mt][nt], pAh[mt][kk], fVl[nt]);
                    mma_bf(acc[mt][nt], pAl[mt][kk], fVh[nt]);
                }
        }
    }

    #pragma unroll
    for (int mt = 0; mt < 2; mt++) {
        rsum[mt][0] += __shfl_xor_sync(0xffffffffu, rsum[mt][0], 1);
        rsum[mt][0] += __shfl_xor_sync(0xffffffffu, rsum[mt][0], 2);
        rsum[mt][1] += __shfl_xor_sync(0xffffffffu, rsum[mt][1], 1);
        rsum[mt][1] += __shfl_xor_sync(0xffffffffu, rsum[mt][1], 2);
    }
    #pragma unroll
    for (int mt = 0; mt < 2; mt++) {
        const float inv0 = 1.0f / rsum[mt][0];
        const float inv1 = 1.0f / rsum[mt][1];
        #pragma unroll
        for (int nt = 0; nt < 8; nt++) {
            int rq_ = qm + mt*16 + (lane >> 2);
            int col = nt*8 + (lane & 3) * 2;
            size_t o0 = (size_t)(bt * SEQ + rq_) * GK + h * HD + col;
            size_t o1 = o0 + (size_t)8 * GK;
            *(__half2*)(g_a16 + o0) =
                __floats2half2_rn(acc[mt][nt][0] * inv0, acc[mt][nt][1] * inv0);
            *(__half2*)(g_a16 + o1) =
                __floats2half2_rn(acc[mt][nt][2] * inv1, acc[mt][nt][3] * inv1);
        }
    }
}

// ---------------------------------------------------------------------------
// launch
// ---------------------------------------------------------------------------
extern "C" void kernel_launch(void* const* d_in, const int* in_sizes, int n_in,
                              void* d_out, int out_size)
{
    const float* x  = (const float*)d_in[0];
    const float* Wq = (const float*)d_in[1];
    const float* Wk = (const float*)d_in[2];
    const float* Wv = (const float*)d_in[3];
    const float* Wo = (const float*)d_in[4];
    const float* qw = (const float*)d_in[5];
    const float* kw = (const float*)d_in[6];
    float* out = (float*)d_out;

    static __half *x16 = nullptr, *a16, *w1h, *w1l, *w2h, *w2l;
    if (!x16) {
        cudaGetSymbolAddress((void**)&x16, g_x16);
        cudaGetSymbolAddress((void**)&a16, g_a16);
        cudaGetSymbolAddress((void**)&w1h, g_w1h);
        cudaGetSymbolAddress((void**)&w1l, g_w1l);
        cudaGetSymbolAddress((void**)&w2h, g_w2h);
        cudaGetSymbolAddress((void**)&w2l, g_w2l);
        cudaFuncSetAttribute(attn_mma,
                             cudaFuncAttributeMaxDynamicSharedMemorySize, ATT_SMEM);
        cudaFuncSetAttribute(gemm_mma<0>,
                             cudaFuncAttributeMaxDynamicSharedMemorySize, SMEM_GEMM);
        cudaFuncSetAttribute(gemm_mma<1>,
                             cudaFuncAttributeMaxDynamicSharedMemorySize, SMEM_GEMM);
    }

    const int n4 = MROWS * GK / 4;
    cvt_half<<<(n4 + 255) / 256, 256>>>(x, x16, n4);
    xpose_qkv<<<(QKVC * GK + 255) / 256, 256>>>(Wq, Wk, Wv, w1h, w1l);
    xpose_wo<<<(DIM * GK + 255) / 256, 256>>>(Wo, w2h, w2l);

    gemm_mma<1><<<dim3(QKVC / 128, MROWS / 128), 128, SMEM_GEMM>>>(
        x16, w1h, w1l, nullptr, 0, qw, kw);

    attn_mma<<<dim3(NH, BTN), 256, ATT_SMEM>>>();

    gemm_mma<0><<<dim3(DIM / 128, MROWS / 128), 128, SMEM_GEMM>>>(
        a16, w2h, w2l, out, DIM, nullptr, nullptr);
}

// round 9
// speedup vs baseline: 1.4607x; 1.0068x over previous
#include <cuda_runtime.h>
#include <cuda_bf16.h>
#include <cuda_fp16.h>
#include <math.h>
#include <stdint.h>

// Problem constants
#define BTN   128
#define SEQ   256
#define DIM   1024
#define NH    16
#define NKV   4
#define GRP   4
#define HD    64
#define MROWS (BTN*SEQ)      // 32768
#define QKVC  1536
#define GK    1024
#define EPSV  1e-6f
#define SCALEV 0.125f
#define CAPV  50.0f

// ---------------------------------------------------------------------------
// Scratch (device globals)
// ---------------------------------------------------------------------------
__device__ __align__(16) __half g_x16[(size_t)MROWS * GK];        // x as fp16
__device__ __align__(16) __half g_a16[(size_t)MROWS * GK];        // attn out fp16
__device__ __align__(16) __half g_w1h[(size_t)QKVC * GK];         // [n][k] hi
__device__ __align__(16) __half g_w1l[(size_t)QKVC * GK];         // [n][k] lo
__device__ __align__(16) __half g_w2h[(size_t)DIM * GK];
__device__ __align__(16) __half g_w2l[(size_t)DIM * GK];
// attention tiles (bf16 hi/lo)
__device__ __align__(16) __nv_bfloat16 g_qth[(size_t)MROWS * GK];
__device__ __align__(16) __nv_bfloat16 g_qtl[(size_t)MROWS * GK];
__device__ __align__(16) __nv_bfloat16 g_kh[(size_t)MROWS * 256];
__device__ __align__(16) __nv_bfloat16 g_kl[(size_t)MROWS * 256];
__device__ __align__(16) __nv_bfloat16 g_vh[(size_t)MROWS * 256];
__device__ __align__(16) __nv_bfloat16 g_vl[(size_t)MROWS * 256];

// ---------------------------------------------------------------------------
// helpers
// ---------------------------------------------------------------------------
__device__ __forceinline__ uint32_t smem_u32(const void* p) {
    uint32_t a;
    asm("{ .reg .u64 t; cvta.to.shared.u64 t, %1; cvt.u32.u64 %0, t; }"
        : "=r"(a) : "l"(p));
    return a;
}
__device__ __forceinline__ void cp16(uint32_t dst, const void* src) {
    asm volatile("cp.async.cg.shared.global [%0], [%1], 16;" :: "r"(dst), "l"(src));
}
__device__ __forceinline__ void ldmx4(uint32_t r[4], uint32_t addr) {
    asm volatile("ldmatrix.sync.aligned.m8n8.x4.shared.b16 {%0,%1,%2,%3}, [%4];"
                 : "=r"(r[0]), "=r"(r[1]), "=r"(r[2]), "=r"(r[3]) : "r"(addr));
}
__device__ __forceinline__ void ldmx4t(uint32_t r[4], uint32_t addr) {
    asm volatile("ldmatrix.sync.aligned.m8n8.x4.trans.shared.b16 {%0,%1,%2,%3}, [%4];"
                 : "=r"(r[0]), "=r"(r[1]), "=r"(r[2]), "=r"(r[3]) : "r"(addr));
}
__device__ __forceinline__ void mma_bf(float c[4], const uint32_t a[4],
                                       const uint32_t b[2]) {
    asm volatile("mma.sync.aligned.m16n8k16.row.col.f32.bf16.bf16.f32 "
                 "{%0,%1,%2,%3}, {%4,%5,%6,%7}, {%8,%9}, {%0,%1,%2,%3};"
                 : "+f"(c[0]), "+f"(c[1]), "+f"(c[2]), "+f"(c[3])
                 : "r"(a[0]), "r"(a[1]), "r"(a[2]), "r"(a[3]),
                   "r"(b[0]), "r"(b[1]));
}
__device__ __forceinline__ void mma_fp(float c[4], const uint32_t a[4],
                                       const uint32_t b[2]) {
    asm volatile("mma.sync.aligned.m16n8k16.row.col.f32.f16.f16.f32 "
                 "{%0,%1,%2,%3}, {%4,%5,%6,%7}, {%8,%9}, {%0,%1,%2,%3};"
                 : "+f"(c[0]), "+f"(c[1]), "+f"(c[2]), "+f"(c[3])
                 : "r"(a[0]), "r"(a[1]), "r"(a[2]), "r"(a[3]),
                   "r"(b[0]), "r"(b[1]));
}
__device__ __forceinline__ void split2(float a, float b, uint32_t& H, uint32_t& L) {
    __nv_bfloat16 ah = __float2bfloat16(a), bh = __float2bfloat16(b);
    __nv_bfloat162 hh(ah, bh);
    H = *(uint32_t*)&hh;
    __nv_bfloat162 ll(__float2bfloat16(a - __bfloat162float(ah)),
                      __float2bfloat16(b - __bfloat162float(bh)));
    L = *(uint32_t*)&ll;
}
#define ASW(o) ((o) ^ (((o) >> 3) & 0x70))

// ---------------------------------------------------------------------------
// conversions
// ---------------------------------------------------------------------------
__global__ void cvt_half(const float* __restrict__ in,
                         __half* __restrict__ out, int n4)
{
    int i = blockIdx.x * blockDim.x + threadIdx.x;
    if (i >= n4) return;
    float4 v = ((const float4*)in)[i];
    __half2* op = (__half2*)out;
    op[2*i]   = __floats2half2_rn(v.x, v.y);
    op[2*i+1] = __floats2half2_rn(v.z, v.w);
}

__global__ void xpose_qkv(const float* __restrict__ Wq, const float* __restrict__ Wk,
                          const float* __restrict__ Wv,
                          __half* __restrict__ th, __half* __restrict__ tl)
{
    size_t idx = (size_t)blockIdx.x * blockDim.x + threadIdx.x;
    if (idx >= (size_t)QKVC * GK) return;
    int k = (int)(idx & (GK - 1));
    int n = (int)(idx >> 10);
    float v;
    if (n < DIM)            v = Wq[(size_t)k * (NH*HD)  + n];
    else if (n < DIM + 256) v = Wk[(size_t)k * (NKV*HD) + (n - DIM)];
    else                    v = Wv[(size_t)k * (NKV*HD) + (n - DIM - 256)];
    __half hv = __float2half_rn(v);
    th[idx] = hv;
    tl[idx] = __float2half_rn(v - __half2float(hv));
}

__global__ void xpose_wo(const float* __restrict__ W,
                         __half* __restrict__ th, __half* __restrict__ tl)
{
    size_t idx = (size_t)blockIdx.x * blockDim.x + threadIdx.x;
    if (idx >= (size_t)DIM * GK) return;
    int k = (int)(idx & (GK - 1));
    int n = (int)(idx >> 10);
    float v = W[(size_t)k * DIM + n];
    __half hv = __float2half_rn(v);
    th[idx] = hv;
    tl[idx] = __float2half_rn(v - __half2float(hv));
}

// ---------------------------------------------------------------------------
// fp16 2-term GEMM: C[m,n] = A[m,:].(Bh[n,:]+Bl[n,:]),  K=1024
// 128x128 CTA tile, 8 warps (32x64 warp tiles), BK=32, 3-stage, 2 CTAs/SM.
// EPI=0: plain fp32 store.  EPI=1: QKV epilogue (rmsnorm fold + bf16 split).
// ---------------------------------------------------------------------------
#define BK      32
#define NCHUNK  (GK / BK)
#define ROWB    80
#define TILE_B  (128 * ROWB)          // 10240
#define OFF_A   0
#define OFF_BH  TILE_B
#define OFF_BL  (2*TILE_B)
#define STG     (3*TILE_B)            // 30720
#define SMEM_GEMM (3 * STG + 1024)    // 93184

__device__ __forceinline__ void g_load(uint32_t sbase, int tid,
    const __half* A, const __half* Bh, const __half* Bl, int koff)
{
    #pragma unroll
    for (int it = 0; it < 2; it++) {
        int idx = tid + it * 256;
        int row = idx >> 2;
        int c4  = idx & 3;
        uint32_t dst = sbase + row * ROWB + c4 * 16;
        size_t so = (size_t)row * GK + koff + c4 * 8;
        cp16(dst + OFF_A,  A  + so);
        cp16(dst + OFF_BH, Bh + so);
        cp16(dst + OFF_BL, Bl + so);
    }
    asm volatile("cp.async.commit_group;" ::: "memory");
}

template<int EPI>
__global__ void __launch_bounds__(256, 2)
gemm_mma(const __half* __restrict__ a, const __half* __restrict__ bh,
         const __half* __restrict__ bl, float* __restrict__ C, int ldc,
         const float* __restrict__ qw, const float* __restrict__ kw)
{
    extern __shared__ char smem_raw[];
    uint32_t sbr = smem_u32(smem_raw);
    const uint32_t sb = (sbr + 1023) & ~1023u;
    const int tid  = threadIdx.x;
    const int wid  = tid >> 5;
    const int lane = tid & 31;
    const int bm = blockIdx.y * 128;
    const int bn = blockIdx.x * 128;

    const __half* A  = a  + (size_t)bm * GK;
    const __half* Bh = bh + (size_t)bn * GK;
    const __half* Bl = bl + (size_t)bn * GK;

    const int wm = (wid & 3) * 32;       // 4 m positions
    const int wn = (wid >> 2) * 64;      // 2 n positions
    const int ar = lane & 15;
    const int ac = (lane >> 4) * 16;

    float acc[2][8][4];
    #pragma unroll
    for (int i = 0; i < 2; i++)
        #pragma unroll
        for (int j = 0; j < 8; j++)
            #pragma unroll
            for (int e = 0; e < 4; e++) acc[i][j][e] = 0.f;

    g_load(sb,       tid, A, Bh, Bl, 0);
    g_load(sb + STG, tid, A, Bh, Bl, BK);

    for (int c = 0; c < NCHUNK; c++) {
        if (c + 1 < NCHUNK)
            asm volatile("cp.async.wait_group 1;" ::: "memory");
        else
            asm volatile("cp.async.wait_group 0;" ::: "memory");
        __syncthreads();
        if (c + 2 < NCHUNK)
            g_load(sb + ((c + 2) % 3) * STG, tid, A, Bh, Bl, (c + 2) * BK);

        const uint32_t st = sb + (c % 3) * STG;
        #pragma unroll
        for (int kk = 0; kk < 2; kk++) {
            const int kb = kk * 32;
            uint32_t fA[2][4];
            #pragma unroll
            for (int mt = 0; mt < 2; mt++) {
                uint32_t arow = (uint32_t)(wm + mt * 16 + ar) * ROWB + kb + ac;
                ldmx4(fA[mt], st + OFF_A + arow);
            }
            #pragma unroll
            for (int half = 0; half < 2; half++) {
                uint32_t fBh[4][2], fBl[4][2];
                #pragma unroll
                for (int np = 0; np < 2; np++) {
                    uint32_t brow = (uint32_t)(wn + (half * 2 + np) * 16
                                    + (lane & 7) + ((lane >> 4) & 1) * 8) * ROWB
                                    + kb + ((lane >> 3) & 1) * 16;
                    uint32_t t[4];
                    ldmx4(t, st + OFF_BH + brow);
                    fBh[np*2][0] = t[0]; fBh[np*2][1] = t[1];
                    fBh[np*2+1][0] = t[2]; fBh[np*2+1][1] = t[3];
                    ldmx4(t, st + OFF_BL + brow);
                    fBl[np*2][0] = t[0]; fBl[np*2][1] = t[1];
                    fBl[np*2+1][0] = t[2]; fBl[np*2+1][1] = t[3];
                }
                #pragma unroll
                for (int mt = 0; mt < 2; mt++)
                    #pragma unroll
                    for (int j = 0; j < 4; j++) {
                        const int nt = half * 4 + j;
                        mma_fp(acc[mt][nt], fA[mt], fBh[j]);
                        mma_fp(acc[mt][nt], fA[mt], fBl[j]);
                    }
            }
        }
    }

    const int er = lane >> 2;
    const int ec = (lane & 3) * 2;

    if (EPI == 0) {
        #pragma unroll
        for (int mt = 0; mt < 2; mt++)
            #pragma unroll
            for (int nt = 0; nt < 8; nt++) {
                size_t row0 = (size_t)(bm + wm + mt * 16 + er) * ldc
                            + bn + wn + nt * 8 + ec;
                *(float2*)&C[row0]           = make_float2(acc[mt][nt][0], acc[mt][nt][1]);
                *(float2*)&C[row0 + 8 * ldc] = make_float2(acc[mt][nt][2], acc[mt][nt][3]);
            }
        return;
    }

    // ---- EPI == 1: QKV epilogue with fused rmsnorm + bf16 hi/lo split ----
    const int gn = bn + wn;            // multiple of 64; head-aligned
    float wqk[16];
    if (gn < DIM) {
        #pragma unroll
        for (int nt = 0; nt < 8; nt++) {
            int col = nt * 8 + ec;
            wqk[2*nt]   = __ldg(&qw[col])   * __ldg(&kw[col]);
            wqk[2*nt+1] = __ldg(&qw[col+1]) * __ldg(&kw[col+1]);
        }
    }

    #pragma unroll
    for (int mt = 0; mt < 2; mt++) {
        #pragma unroll
        for (int hf = 0; hf < 2; hf++) {
            const int grow = bm + wm + mt * 16 + er + hf * 8;
            const int bt = grow >> 8;
            const int s  = grow & 255;
            float v[16];
            #pragma unroll
            for (int nt = 0; nt < 8; nt++) {
                v[2*nt]   = acc[mt][nt][hf*2];
                v[2*nt+1] = acc[mt][nt][hf*2+1];
            }
            __nv_bfloat16 *dh, *dl;
            size_t dbase;
            if (gn < DIM) {                    // Q: rmsnorm + qw*kw + scales
                float ssq = 0.f;
                #pragma unroll
                for (int j = 0; j < 16; j++) ssq += v[j] * v[j];
                ssq += __shfl_xor_sync(0xffffffffu, ssq, 1);
                ssq += __shfl_xor_sync(0xffffffffu, ssq, 2);
                float r = rsqrtf(ssq * (1.0f / HD) + EPSV) * (SCALEV * 2.0f / CAPV);
                #pragma unroll
                for (int j = 0; j < 16; j++) v[j] *= r * wqk[j];
                int h = gn >> 6;
                dh = g_qth; dl = g_qtl;
                dbase = ((size_t)(bt * NH + h) * SEQ + s) * HD;
            } else if (gn < DIM + 256) {       // K: rmsnorm only
                float ssq = 0.f;
                #pragma unroll
                for (int j = 0; j < 16; j++) ssq += v[j] * v[j];
                ssq += __shfl_xor_sync(0xffffffffu, ssq, 1);
                ssq += __shfl_xor_sync(0xffffffffu, ssq, 2);
                float r = rsqrtf(ssq * (1.0f / HD) + EPSV);
                #pragma unroll
                for (int j = 0; j < 16; j++) v[j] *= r;
                int kvh = (gn - DIM) >> 6;
                dh = g_kh; dl = g_kl;
                dbase = ((size_t)(bt * NKV + kvh) * SEQ + s) * HD;
            } else {                            // V: plain
                int kvh = (gn - DIM - 256) >> 6;
                dh = g_vh; dl = g_vl;
                dbase = ((size_t)(bt * NKV + kvh) * SEQ + s) * HD;
            }
            #pragma unroll
            for (int nt = 0; nt < 8; nt++) {
                uint32_t H, L;
                split2(v[2*nt], v[2*nt+1], H, L);
                *(uint32_t*)(dh + dbase + nt * 8 + ec) = H;
                *(uint32_t*)(dl + dbase + nt * 8 + ec) = L;
            }
        }
    }
}

// ---------------------------------------------------------------------------
// Tensor-core attention: block per (bt, h), 256 threads (8 warps). bf16x3.
// ---------------------------------------------------------------------------
#define ATT_SMEM (6 * 32768 + 1024)

__global__ void __launch_bounds__(256, 1)
attn_mma()
{
    extern __shared__ char smem_raw[];
    uint32_t sbr = smem_u32(smem_raw);
    const uint32_t sb = (sbr + 1023) & ~1023u;
    const uint32_t sQh = sb, sQl = sb + 32768, sKh = sb + 65536,
                   sKl = sb + 98304, sVh = sb + 131072, sVl = sb + 163840;

    const int h  = blockIdx.x;
    const int bt = blockIdx.y;
    const int kvh = h >> 2;
    const int tid = threadIdx.x;
    const int lane = tid & 31;
    const int wid = tid >> 5;

    {
        const size_t qoff = (size_t)(bt * NH + h) * SEQ * HD;
        const size_t koff = (size_t)(bt * NKV + kvh) * SEQ * HD;
        const __nv_bfloat16* srcs[6] = {
            g_qth + qoff, g_qtl + qoff, g_kh + koff, g_kl + koff,
            g_vh + koff, g_vl + koff };
        #pragma unroll
        for (int t = 0; t < 6; t++) {
            const __nv_bfloat16* s = srcs[t];
            const uint32_t dtile = sb + t * 32768;
            #pragma unroll
            for (int i = 0; i < 8; i++) {
                uint32_t q = tid + i * 256;
                uint32_t row = q >> 3, j = q & 7;
                cp16(dtile + ASW(row * 128 + j * 16), s + row * 64 + j * 8);
            }
        }
        asm volatile("cp.async.commit_group;" ::: "memory");
        asm volatile("cp.async.wait_group 0;" ::: "memory");
    }
    __syncthreads();

    const int qm = wid * 32;
    float acc[2][8][4];
    float rsum[2][2];
    #pragma unroll
    for (int i = 0; i < 2; i++) {
        rsum[i][0] = rsum[i][1] = 0.f;
        #pragma unroll
        for (int j = 0; j < 8; j++)
            #pragma unroll
            for (int e = 0; e < 4; e++) acc[i][j][e] = 0.f;
    }

    for (int kb = 0; kb < 4; kb++) {
        float S[2][8][4];
        #pragma unroll
        for (int i = 0; i < 2; i++)
            #pragma unroll
            for (int j = 0; j < 8; j++)
                #pragma unroll
                for (int e = 0; e < 4; e++) S[i][j][e] = 0.f;

        #pragma unroll
        for (int ks = 0; ks < 4; ks++) {
            uint32_t fQh[2][4], fQl[2][4];
            #pragma unroll
            for (int mt = 0; mt < 2; mt++) {
                uint32_t off = ASW((uint32_t)((qm + mt*16 + (lane & 15)) * 128
                              + ks * 32 + ((lane >> 4) & 1) * 16));
                ldmx4(fQh[mt], sQh + off);
                ldmx4(fQl[mt], sQl + off);
            }
            uint32_t fKh[8][2], fKl[8][2];
            #pragma unroll
            for (int np = 0; np < 4; np++) {
                uint32_t krow = kb*64 + np*16 + (lane & 7) + ((lane >> 4) & 1) * 8;
                uint32_t off = ASW(krow * 128 + ks * 32 + ((lane >> 3) & 1) * 16);
                uint32_t t[4];
                ldmx4(t, sKh + off);
                fKh[2*np][0] = t[0]; fKh[2*np][1] = t[1];
                fKh[2*np+1][0] = t[2]; fKh[2*np+1][1] = t[3];
                ldmx4(t, sKl + off);
                fKl[2*np][0] = t[0]; fKl[2*np][1] = t[1];
                fKl[2*np+1][0] = t[2]; fKl[2*np+1][1] = t[3];
            }
            #pragma unroll
            for (int mt = 0; mt < 2; mt++)
                #pragma unroll
                for (int nt = 0; nt < 8; nt++) {
                    mma_bf(S[mt][nt], fQh[mt], fKh[nt]);
                    mma_bf(S[mt][nt], fQh[mt], fKl[nt]);
                    mma_bf(S[mt][nt], fQl[mt], fKh[nt]);
                }
        }

        uint32_t pAh[2][4][4], pAl[2][4][4];
        #pragma unroll
        for (int mt = 0; mt < 2; mt++) {
            #pragma unroll
            for (int nt = 0; nt < 8; nt++) {
                #pragma unroll
                for (int e = 0; e < 4; e++) {
                    float uu = __expf(S[mt][nt][e]);
                    S[mt][nt][e] = __expf(__fdividef(-2.0f * CAPV, uu + 1.0f));
                }
                rsum[mt][0] += S[mt][nt][0] + S[mt][nt][1];
                rsum[mt][1] += S[mt][nt][2] + S[mt][nt][3];
            }
            #pragma unroll
            for (int kk = 0; kk < 4; kk++) {
                split2(S[mt][2*kk][0],   S[mt][2*kk][1],   pAh[mt][kk][0], pAl[mt][kk][0]);
                split2(S[mt][2*kk][2],   S[mt][2*kk][3],   pAh[mt][kk][1], pAl[mt][kk][1]);
                split2(S[mt][2*kk+1][0], S[mt][2*kk+1][1], pAh[mt][kk][2], pAl[mt][kk][2]);
                split2(S[mt][2*kk+1][2], S[mt][2*kk+1][3], pAh[mt][kk][3], pAl[mt][kk][3]);
            }
        }

        #pragma unroll
        for (int kk = 0; kk < 4; kk++) {
            uint32_t fVh[8][2], fVl[8][2];
            #pragma unroll
            for (int np = 0; np < 4; np++) {
                uint32_t vrow = kb*64 + kk*16 + (lane & 7) + ((lane >> 3) & 1) * 8;
                uint32_t off = ASW(vrow * 128 + (np*16 + ((lane >> 4) & 1) * 8) * 2);
                uint32_t t[4];
                ldmx4t(t, sVh + off);
                fVh[2*np][0] = t[0]; fVh[2*np][1] = t[1];
                fVh[2*np+1][0] = t[2]; fVh[2*np+1][1] = t[3];
                ldmx4t(t, sVl + off);
                fVl[2*np][0] = t[0]; fVl[2*np][1] = t[1];
                fVl[2*np+1][0] = t[2]; fVl[2*np+1][1] = t[3];
            }
            #pragma unroll
            for (int mt = 0; mt < 2; mt++)
                #pragma unroll
                for (int nt = 0; nt < 8; nt++) {
                    mma_bf(acc[mt][nt], pAh[mt][kk], fVh[nt]);
                    mma_bf(acc[mt][nt], pAh[mt][kk], fVl[nt]);
                    mma_bf(acc[mt][nt], pAl[mt][kk], fVh[nt]);
                }
        }
    }

    #pragma unroll
    for (int mt = 0; mt < 2; mt++) {
        rsum[mt][0] += __shfl_xor_sync(0xffffffffu, rsum[mt][0], 1);
        rsum[mt][0] += __shfl_xor_sync(0xffffffffu, rsum[mt][0], 2);
        rsum[mt][1] += __shfl_xor_sync(0xffffffffu, rsum[mt][1], 1);
        rsum[mt][1] += __shfl_xor_sync(0xffffffffu, rsum[mt][1], 2);
    }
    #pragma unroll
    for (int mt = 0; mt < 2; mt++) {
        const float inv0 = 1.0f / rsum[mt][0];
        const float inv1 = 1.0f / rsum[mt][1];
        #pragma unroll
        for (int nt = 0; nt < 8; nt++) {
            int rq_ = qm + mt*16 + (lane >> 2);
            int col = nt*8 + (lane & 3) * 2;
            size_t o0 = (size_t)(bt * SEQ + rq_) * GK + h * HD + col;
            size_t o1 = o0 + (size_t)8 * GK;
            *(__half2*)(g_a16 + o0) =
                __floats2half2_rn(acc[mt][nt][0] * inv0, acc[mt][nt][1] * inv0);
            *(__half2*)(g_a16 + o1) =
                __floats2half2_rn(acc[mt][nt][2] * inv1, acc[mt][nt][3] * inv1);
        }
    }
}

// ---------------------------------------------------------------------------
// launch
// ---------------------------------------------------------------------------
extern "C" void kernel_launch(void* const* d_in, const int* in_sizes, int n_in,
                              void* d_out, int out_size)
{
    const float* x  = (const float*)d_in[0];
    const float* Wq = (const float*)d_in[1];
    const float* Wk = (const float*)d_in[2];
    const float* Wv = (const float*)d_in[3];
    const float* Wo = (const float*)d_in[4];
    const float* qw = (const float*)d_in[5];
    const float* kw = (const float*)d_in[6];
    float* out = (float*)d_out;

    static __half *x16 = nullptr, *a16, *w1h, *w1l, *w2h, *w2l;
    if (!x16) {
        cudaGetSymbolAddress((void**)&x16, g_x16);
        cudaGetSymbolAddress((void**)&a16, g_a16);
        cudaGetSymbolAddress((void**)&w1h, g_w1h);
        cudaGetSymbolAddress((void**)&w1l, g_w1l);
        cudaGetSymbolAddress((void**)&w2h, g_w2h);
        cudaGetSymbolAddress((void**)&w2l, g_w2l);
        cudaFuncSetAttribute(attn_mma,
                             cudaFuncAttributeMaxDynamicSharedMemorySize, ATT_SMEM);
        cudaFuncSetAttribute(gemm_mma<0>,
                             cudaFuncAttributeMaxDynamicSharedMemorySize, SMEM_GEMM);
        cudaFuncSetAttribute(gemm_mma<1>,
                             cudaFuncAttributeMaxDynamicSharedMemorySize, SMEM_GEMM);
    }

    const int n4 = MROWS * GK / 4;
    cvt_half<<<(n4 + 255) / 256, 256>>>(x, x16, n4);
    xpose_qkv<<<(QKVC * GK + 255) / 256, 256>>>(Wq, Wk, Wv, w1h, w1l);
    xpose_wo<<<(DIM * GK + 255) / 256, 256>>>(Wo, w2h, w2l);

    gemm_mma<1><<<dim3(QKVC / 128, MROWS / 128), 256, SMEM_GEMM>>>(
        x16, w1h, w1l, nullptr, 0, qw, kw);

    attn_mma<<<dim3(NH, BTN), 256, ATT_SMEM>>>();

    gemm_mma<0><<<dim3(DIM / 128, MROWS / 128), 256, SMEM_GEMM>>>(
        a16, w2h, w2l, out, DIM, nullptr, nullptr);
}

// round 10
// speedup vs baseline: 1.7926x; 1.2272x over previous
#include <cuda_runtime.h>
#include <cuda_bf16.h>
#include <cuda_fp16.h>
#include <math.h>
#include <stdint.h>

// Problem constants
#define BTN   128
#define SEQ   256
#define DIM   1024
#define NH    16
#define NKV   4
#define GRP   4
#define HD    64
#define MROWS (BTN*SEQ)      // 32768
#define QKVC  1536
#define GK    1024
#define EPSV  1e-6f
#define SCALEV 0.125f
#define CAPV  50.0f

// ---------------------------------------------------------------------------
// Scratch (device globals)
// ---------------------------------------------------------------------------
__device__ __align__(16) __half g_x16[(size_t)MROWS * GK];        // x as fp16
__device__ __align__(16) __half g_a16[(size_t)MROWS * GK];        // attn out fp16
__device__ __align__(16) __half g_w1h[(size_t)QKVC * GK];         // [n][k] hi
__device__ __align__(16) __half g_w1l[(size_t)QKVC * GK];         // [n][k] lo
__device__ __align__(16) __half g_w2h[(size_t)DIM * GK];
__device__ __align__(16) __half g_w2l[(size_t)DIM * GK];
// attention tiles (bf16 hi/lo)
__device__ __align__(16) __nv_bfloat16 g_qth[(size_t)MROWS * GK];
__device__ __align__(16) __nv_bfloat16 g_qtl[(size_t)MROWS * GK];
__device__ __align__(16) __nv_bfloat16 g_kh[(size_t)MROWS * 256];
__device__ __align__(16) __nv_bfloat16 g_kl[(size_t)MROWS * 256];
__device__ __align__(16) __nv_bfloat16 g_vh[(size_t)MROWS * 256];
__device__ __align__(16) __nv_bfloat16 g_vl[(size_t)MROWS * 256];

// ---------------------------------------------------------------------------
// helpers
// ---------------------------------------------------------------------------
__device__ __forceinline__ uint32_t smem_u32(const void* p) {
    uint32_t a;
    asm("{ .reg .u64 t; cvta.to.shared.u64 t, %1; cvt.u32.u64 %0, t; }"
        : "=r"(a) : "l"(p));
    return a;
}
__device__ __forceinline__ void cp16(uint32_t dst, const void* src) {
    asm volatile("cp.async.cg.shared.global [%0], [%1], 16;" :: "r"(dst), "l"(src));
}
__device__ __forceinline__ void ldmx4(uint32_t r[4], uint32_t addr) {
    asm volatile("ldmatrix.sync.aligned.m8n8.x4.shared.b16 {%0,%1,%2,%3}, [%4];"
                 : "=r"(r[0]), "=r"(r[1]), "=r"(r[2]), "=r"(r[3]) : "r"(addr));
}
__device__ __forceinline__ void ldmx4t(uint32_t r[4], uint32_t addr) {
    asm volatile("ldmatrix.sync.aligned.m8n8.x4.trans.shared.b16 {%0,%1,%2,%3}, [%4];"
                 : "=r"(r[0]), "=r"(r[1]), "=r"(r[2]), "=r"(r[3]) : "r"(addr));
}
__device__ __forceinline__ void mma_bf(float c[4], const uint32_t a[4],
                                       const uint32_t b[2]) {
    asm volatile("mma.sync.aligned.m16n8k16.row.col.f32.bf16.bf16.f32 "
                 "{%0,%1,%2,%3}, {%4,%5,%6,%7}, {%8,%9}, {%0,%1,%2,%3};"
                 : "+f"(c[0]), "+f"(c[1]), "+f"(c[2]), "+f"(c[3])
                 : "r"(a[0]), "r"(a[1]), "r"(a[2]), "r"(a[3]),
                   "r"(b[0]), "r"(b[1]));
}
__device__ __forceinline__ void mma_fp(float c[4], const uint32_t a[4],
                                       const uint32_t b[2]) {
    asm volatile("mma.sync.aligned.m16n8k16.row.col.f32.f16.f16.f32 "
                 "{%0,%1,%2,%3}, {%4,%5,%6,%7}, {%8,%9}, {%0,%1,%2,%3};"
                 : "+f"(c[0]), "+f"(c[1]), "+f"(c[2]), "+f"(c[3])
                 : "r"(a[0]), "r"(a[1]), "r"(a[2]), "r"(a[3]),
                   "r"(b[0]), "r"(b[1]));
}
__device__ __forceinline__ void split2(float a, float b, uint32_t& H, uint32_t& L) {
    __nv_bfloat16 ah = __float2bfloat16(a), bh = __float2bfloat16(b);
    __nv_bfloat162 hh(ah, bh);
    H = *(uint32_t*)&hh;
    __nv_bfloat162 ll(__float2bfloat16(a - __bfloat162float(ah)),
                      __float2bfloat16(b - __bfloat162float(bh)));
    L = *(uint32_t*)&ll;
}
#define ASW(o) ((o) ^ (((o) >> 3) & 0x70))

// ---------------------------------------------------------------------------
// conversions
// ---------------------------------------------------------------------------
__global__ void cvt_half(const float* __restrict__ in,
                         __half* __restrict__ out, int n4)
{
    int i = blockIdx.x * blockDim.x + threadIdx.x;
    if (i >= n4) return;
    float4 v = ((const float4*)in)[i];
    __half2* op = (__half2*)out;
    op[2*i]   = __floats2half2_rn(v.x, v.y);
    op[2*i+1] = __floats2half2_rn(v.z, v.w);
}

__global__ void xpose_qkv(const float* __restrict__ Wq, const float* __restrict__ Wk,
                          const float* __restrict__ Wv,
                          __half* __restrict__ th, __half* __restrict__ tl)
{
    size_t idx = (size_t)blockIdx.x * blockDim.x + threadIdx.x;
    if (idx >= (size_t)QKVC * GK) return;
    int k = (int)(idx & (GK - 1));
    int n = (int)(idx >> 10);
    float v;
    if (n < DIM)            v = Wq[(size_t)k * (NH*HD)  + n];
    else if (n < DIM + 256) v = Wk[(size_t)k * (NKV*HD) + (n - DIM)];
    else                    v = Wv[(size_t)k * (NKV*HD) + (n - DIM - 256)];
    __half hv = __float2half_rn(v);
    th[idx] = hv;
    tl[idx] = __float2half_rn(v - __half2float(hv));
}

__global__ void xpose_wo(const float* __restrict__ W,
                         __half* __restrict__ th, __half* __restrict__ tl)
{
    size_t idx = (size_t)blockIdx.x * blockDim.x + threadIdx.x;
    if (idx >= (size_t)DIM * GK) return;
    int k = (int)(idx & (GK - 1));
    int n = (int)(idx >> 10);
    float v = W[(size_t)k * DIM + n];
    __half hv = __float2half_rn(v);
    th[idx] = hv;
    tl[idx] = __float2half_rn(v - __half2float(hv));
}

// ---------------------------------------------------------------------------
// fp16 2-term GEMM: C[m,n] = A[m,:].(Bh[n,:]+Bl[n,:]),  K=1024
// 128x128 CTA tile, 8 warps (32x64 warp tiles), BK=64, 2-stage, SW128
// swizzled smem (128B rows, no padding), 2 CTAs/SM.
// EPI=0: plain fp32 store.  EPI=1: QKV epilogue (rmsnorm fold + bf16 split).
// ---------------------------------------------------------------------------
#define BK      64
#define NCHUNK  (GK / BK)             // 16
#define TILE_B  (128 * 128)           // 16384 (128 rows x 128B)
#define OFF_A   0
#define OFF_BH  TILE_B
#define OFF_BL  (2*TILE_B)
#define STG     (3*TILE_B)            // 49152
#define SMEM_GEMM (2 * STG + 1024)    // 99328

__device__ __forceinline__ void g_load(uint32_t sbase, int tid,
    const __half* A, const __half* Bh, const __half* Bl, int koff)
{
    #pragma unroll
    for (int it = 0; it < 4; it++) {
        int g = tid + it * 256;            // 0..1023 granules per array
        int row = g >> 3;
        int j   = g & 7;
        uint32_t dst = sbase + ASW((uint32_t)(row * 128 + j * 16));
        size_t so = (size_t)row * GK + koff + j * 8;
        cp16(dst + OFF_A,  A  + so);
        cp16(dst + OFF_BH, Bh + so);
        cp16(dst + OFF_BL, Bl + so);
    }
    asm volatile("cp.async.commit_group;" ::: "memory");
}

template<int EPI>
__global__ void __launch_bounds__(256, 2)
gemm_mma(const __half* __restrict__ a, const __half* __restrict__ bh,
         const __half* __restrict__ bl, float* __restrict__ C, int ldc,
         const float* __restrict__ qw, const float* __restrict__ kw)
{
    extern __shared__ char smem_raw[];
    uint32_t sbr = smem_u32(smem_raw);
    const uint32_t sb = (sbr + 1023) & ~1023u;
    const int tid  = threadIdx.x;
    const int wid  = tid >> 5;
    const int lane = tid & 31;
    const int bm = blockIdx.y * 128;
    const int bn = blockIdx.x * 128;

    const __half* A  = a  + (size_t)bm * GK;
    const __half* Bh = bh + (size_t)bn * GK;
    const __half* Bl = bl + (size_t)bn * GK;

    const int wm = (wid & 3) * 32;       // 4 m positions
    const int wn = (wid >> 2) * 64;      // 2 n positions
    const int ar = lane & 15;
    const int ac = (lane >> 4) * 16;
    const int br = (lane & 7) + ((lane >> 4) & 1) * 8;
    const int bc = ((lane >> 3) & 1) * 16;

    float acc[2][8][4];
    #pragma unroll
    for (int i = 0; i < 2; i++)
        #pragma unroll
        for (int j = 0; j < 8; j++)
            #pragma unroll
            for (int e = 0; e < 4; e++) acc[i][j][e] = 0.f;

    g_load(sb, tid, A, Bh, Bl, 0);

    for (int c = 0; c < NCHUNK; c++) {
        asm volatile("cp.async.wait_group 0;" ::: "memory");
        __syncthreads();
        if (c + 1 < NCHUNK)
            g_load(sb + ((c + 1) & 1) * STG, tid, A, Bh, Bl, (c + 1) * BK);

        const uint32_t st = sb + (c & 1) * STG;
        #pragma unroll
        for (int kk = 0; kk < 4; kk++) {
            const int kb = kk * 32;      // byte offset of this k16 within 128B row
            uint32_t fA[2][4];
            #pragma unroll
            for (int mt = 0; mt < 2; mt++) {
                uint32_t off = ASW((uint32_t)((wm + mt * 16 + ar) * 128 + kb + ac));
                ldmx4(fA[mt], st + OFF_A + off);
            }
            uint32_t fBh[8][2], fBl[8][2];
            #pragma unroll
            for (int g = 0; g < 4; g++) {
                uint32_t off = ASW((uint32_t)((wn + g * 16 + br) * 128 + kb + bc));
                uint32_t t[4];
                ldmx4(t, st + OFF_BH + off);
                fBh[2*g][0] = t[0]; fBh[2*g][1] = t[1];
                fBh[2*g+1][0] = t[2]; fBh[2*g+1][1] = t[3];
                ldmx4(t, st + OFF_BL + off);
                fBl[2*g][0] = t[0]; fBl[2*g][1] = t[1];
                fBl[2*g+1][0] = t[2]; fBl[2*g+1][1] = t[3];
            }
            #pragma unroll
            for (int mt = 0; mt < 2; mt++)
                #pragma unroll
                for (int nt = 0; nt < 8; nt++) {
                    mma_fp(acc[mt][nt], fA[mt], fBh[nt]);
                    mma_fp(acc[mt][nt], fA[mt], fBl[nt]);
                }
        }
    }

    const int er = lane >> 2;
    const int ec = (lane & 3) * 2;

    if (EPI == 0) {
        #pragma unroll
        for (int mt = 0; mt < 2; mt++)
            #pragma unroll
            for (int nt = 0; nt < 8; nt++) {
                size_t row0 = (size_t)(bm + wm + mt * 16 + er) * ldc
                            + bn + wn + nt * 8 + ec;
                *(float2*)&C[row0]           = make_float2(acc[mt][nt][0], acc[mt][nt][1]);
                *(float2*)&C[row0 + 8 * ldc] = make_float2(acc[mt][nt][2], acc[mt][nt][3]);
            }
        return;
    }

    // ---- EPI == 1: QKV epilogue with fused rmsnorm + bf16 hi/lo split ----
    const int gn = bn + wn;            // multiple of 64; head-aligned
    float wqk[16];
    if (gn < DIM) {
        #pragma unroll
        for (int nt = 0; nt < 8; nt++) {
            int col = nt * 8 + ec;
            wqk[2*nt]   = __ldg(&qw[col])   * __ldg(&kw[col]);
            wqk[2*nt+1] = __ldg(&qw[col+1]) * __ldg(&kw[col+1]);
        }
    }

    #pragma unroll
    for (int mt = 0; mt < 2; mt++) {
        #pragma unroll
        for (int hf = 0; hf < 2; hf++) {
            const int grow = bm + wm + mt * 16 + er + hf * 8;
            const int bt = grow >> 8;
            const int s  = grow & 255;
            float v[16];
            #pragma unroll
            for (int nt = 0; nt < 8; nt++) {
                v[2*nt]   = acc[mt][nt][hf*2];
                v[2*nt+1] = acc[mt][nt][hf*2+1];
            }
            __nv_bfloat16 *dh, *dl;
            size_t dbase;
            if (gn < DIM) {                    // Q: rmsnorm + qw*kw + scales
                float ssq = 0.f;
                #pragma unroll
                for (int j = 0; j < 16; j++) ssq += v[j] * v[j];
                ssq += __shfl_xor_sync(0xffffffffu, ssq, 1);
                ssq += __shfl_xor_sync(0xffffffffu, ssq, 2);
                float r = rsqrtf(ssq * (1.0f / HD) + EPSV) * (SCALEV * 2.0f / CAPV);
                #pragma unroll
                for (int j = 0; j < 16; j++) v[j] *= r * wqk[j];
                int h = gn >> 6;
                dh = g_qth; dl = g_qtl;
                dbase = ((size_t)(bt * NH + h) * SEQ + s) * HD;
            } else if (gn < DIM + 256) {       // K: rmsnorm only
                float ssq = 0.f;
                #pragma unroll
                for (int j = 0; j < 16; j++) ssq += v[j] * v[j];
                ssq += __shfl_xor_sync(0xffffffffu, ssq, 1);
                ssq += __shfl_xor_sync(0xffffffffu, ssq, 2);
                float r = rsqrtf(ssq * (1.0f / HD) + EPSV);
                #pragma unroll
                for (int j = 0; j < 16; j++) v[j] *= r;
                int kvh = (gn - DIM) >> 6;
                dh = g_kh; dl = g_kl;
                dbase = ((size_t)(bt * NKV + kvh) * SEQ + s) * HD;
            } else {                            // V: plain
                int kvh = (gn - DIM - 256) >> 6;
                dh = g_vh; dl = g_vl;
                dbase = ((size_t)(bt * NKV + kvh) * SEQ + s) * HD;
            }
            #pragma unroll
            for (int nt = 0; nt < 8; nt++) {
                uint32_t H, L;
                split2(v[2*nt], v[2*nt+1], H, L);
                *(uint32_t*)(dh + dbase + nt * 8 + ec) = H;
                *(uint32_t*)(dl + dbase + nt * 8 + ec) = L;
            }
        }
    }
}

// ---------------------------------------------------------------------------
// Tensor-core attention: block per (bt, h), 256 threads (8 warps). bf16x3.
// ---------------------------------------------------------------------------
#define ATT_SMEM (6 * 32768 + 1024)

__global__ void __launch_bounds__(256, 1)
attn_mma()
{
    extern __shared__ char smem_raw[];
    uint32_t sbr = smem_u32(smem_raw);
    const uint32_t sb = (sbr + 1023) & ~1023u;
    const uint32_t sQh = sb, sQl = sb + 32768, sKh = sb + 65536,
                   sKl = sb + 98304, sVh = sb + 131072, sVl = sb + 163840;

    const int h  = blockIdx.x;
    const int bt = blockIdx.y;
    const int kvh = h >> 2;
    const int tid = threadIdx.x;
    const int lane = tid & 31;
    const int wid = tid >> 5;

    {
        const size_t qoff = (size_t)(bt * NH + h) * SEQ * HD;
        const size_t koff = (size_t)(bt * NKV + kvh) * SEQ * HD;
        const __nv_bfloat16* srcs[6] = {
            g_qth + qoff, g_qtl + qoff, g_kh + koff, g_kl + koff,
            g_vh + koff, g_vl + koff };
        #pragma unroll
        for (int t = 0; t < 6; t++) {
            const __nv_bfloat16* s = srcs[t];
            const uint32_t dtile = sb + t * 32768;
            #pragma unroll
            for (int i = 0; i < 8; i++) {
                uint32_t q = tid + i * 256;
                uint32_t row = q >> 3, j = q & 7;
                cp16(dtile + ASW(row * 128 + j * 16), s + row * 64 + j * 8);
            }
        }
        asm volatile("cp.async.commit_group;" ::: "memory");
        asm volatile("cp.async.wait_group 0;" ::: "memory");
    }
    __syncthreads();

    const int qm = wid * 32;
    float acc[2][8][4];
    float rsum[2][2];
    #pragma unroll
    for (int i = 0; i < 2; i++) {
        rsum[i][0] = rsum[i][1] = 0.f;
        #pragma unroll
        for (int j = 0; j < 8; j++)
            #pragma unroll
            for (int e = 0; e < 4; e++) acc[i][j][e] = 0.f;
    }

    for (int kb = 0; kb < 4; kb++) {
        float S[2][8][4];
        #pragma unroll
        for (int i = 0; i < 2; i++)
            #pragma unroll
            for (int j = 0; j < 8; j++)
                #pragma unroll
                for (int e = 0; e < 4; e++) S[i][j][e] = 0.f;

        #pragma unroll
        for (int ks = 0; ks < 4; ks++) {
            uint32_t fQh[2][4], fQl[2][4];
            #pragma unroll
            for (int mt = 0; mt < 2; mt++) {
                uint32_t off = ASW((uint32_t)((qm + mt*16 + (lane & 15)) * 128
                              + ks * 32 + ((lane >> 4) & 1) * 16));
                ldmx4(fQh[mt], sQh + off);
                ldmx4(fQl[mt], sQl + off);
            }
            uint32_t fKh[8][2], fKl[8][2];
            #pragma unroll
            for (int np = 0; np < 4; np++) {
                uint32_t krow = kb*64 + np*16 + (lane & 7) + ((lane >> 4) & 1) * 8;
                uint32_t off = ASW(krow * 128 + ks * 32 + ((lane >> 3) & 1) * 16);
                uint32_t t[4];
                ldmx4(t, sKh + off);
                fKh[2*np][0] = t[0]; fKh[2*np][1] = t[1];
                fKh[2*np+1][0] = t[2]; fKh[2*np+1][1] = t[3];
                ldmx4(t, sKl + off);
                fKl[2*np][0] = t[0]; fKl[2*np][1] = t[1];
                fKl[2*np+1][0] = t[2]; fKl[2*np+1][1] = t[3];
            }
            #pragma unroll
            for (int mt = 0; mt < 2; mt++)
                #pragma unroll
                for (int nt = 0; nt < 8; nt++) {
                    mma_bf(S[mt][nt], fQh[mt], fKh[nt]);
                    mma_bf(S[mt][nt], fQh[mt], fKl[nt]);
                    mma_bf(S[mt][nt], fQl[mt], fKh[nt]);
                }
        }

        uint32_t pAh[2][4][4], pAl[2][4][4];
        #pragma unroll
        for (int mt = 0; mt < 2; mt++) {
            #pragma unroll
            for (int nt = 0; nt < 8; nt++) {
                #pragma unroll
                for (int e = 0; e < 4; e++) {
                    float uu = __expf(S[mt][nt][e]);
                    S[mt][nt][e] = __expf(__fdividef(-2.0f * CAPV, uu + 1.0f));
                }
                rsum[mt][0] += S[mt][nt][0] + S[mt][nt][1];
                rsum[mt][1] += S[mt][nt][2] + S[mt][nt][3];
            }
            #pragma unroll
            for (int kk = 0; kk < 4; kk++) {
                split2(S[mt][2*kk][0],   S[mt][2*kk][1],   pAh[mt][kk][0], pAl[mt][kk][0]);
                split2(S[mt][2*kk][2],   S[mt][2*kk][3],   pAh[mt][kk][1], pAl[mt][kk][1]);
                split2(S[mt][2*kk+1][0], S[mt][2*kk+1][1], pAh[mt][kk][2], pAl[mt][kk][2]);
                split2(S[mt][2*kk+1][2], S[mt][2*kk+1][3], pAh[mt][kk][3], pAl[mt][kk][3]);
            }
        }

        #pragma unroll
        for (int kk = 0; kk < 4; kk++) {
            uint32_t fVh[8][2], fVl[8][2];
            #pragma unroll
            for (int np = 0; np < 4; np++) {
                uint32_t vrow = kb*64 + kk*16 + (lane & 7) + ((lane >> 3) & 1) * 8;
                uint32_t off = ASW(vrow * 128 + (np*16 + ((lane >> 4) & 1) * 8) * 2);
                uint32_t t[4];
                ldmx4t(t, sVh + off);
                fVh[2*np][0] = t[0]; fVh[2*np][1] = t[1];
                fVh[2*np+1][0] = t[2]; fVh[2*np+1][1] = t[3];
                ldmx4t(t, sVl + off);
                fVl[2*np][0] = t[0]; fVl[2*np][1] = t[1];
                fVl[2*np+1][0] = t[2]; fVl[2*np+1][1] = t[3];
            }
            #pragma unroll
            for (int mt = 0; mt < 2; mt++)
                #pragma unroll
                for (int nt = 0; nt < 8; nt++) {
                    mma_bf(acc[mt][nt], pAh[mt][kk], fVh[nt]);
                    mma_bf(acc[mt][nt], pAh[mt][kk], fVl[nt]);
                    mma_bf(acc[mt][nt], pAl[mt][kk], fVh[nt]);
                }
        }
    }

    #pragma unroll
    for (int mt = 0; mt < 2; mt++) {
        rsum[mt][0] += __shfl_xor_sync(0xffffffffu, rsum[mt][0], 1);
        rsum[mt][0] += __shfl_xor_sync(0xffffffffu, rsum[mt][0], 2);
        rsum[mt][1] += __shfl_xor_sync(0xffffffffu, rsum[mt][1], 1);
        rsum[mt][1] += __shfl_xor_sync(0xffffffffu, rsum[mt][1], 2);
    }
    #pragma unroll
    for (int mt = 0; mt < 2; mt++) {
        const float inv0 = 1.0f / rsum[mt][0];
        const float inv1 = 1.0f / rsum[mt][1];
        #pragma unroll
        for (int nt = 0; nt < 8; nt++) {
            int rq_ = qm + mt*16 + (lane >> 2);
            int col = nt*8 + (lane & 3) * 2;
            size_t o0 = (size_t)(bt * SEQ + rq_) * GK + h * HD + col;
            size_t o1 = o0 + (size_t)8 * GK;
            *(__half2*)(g_a16 + o0) =
                __floats2half2_rn(acc[mt][nt][0] * inv0, acc[mt][nt][1] * inv0);
            *(__half2*)(g_a16 + o1) =
                __floats2half2_rn(acc[mt][nt][2] * inv1, acc[mt][nt][3] * inv1);
        }
    }
}

// ---------------------------------------------------------------------------
// launch
// ---------------------------------------------------------------------------
extern "C" void kernel_launch(void* const* d_in, const int* in_sizes, int n_in,
                              void* d_out, int out_size)
{
    const float* x  = (const float*)d_in[0];
    const float* Wq = (const float*)d_in[1];
    const float* Wk = (const float*)d_in[2];
    const float* Wv = (const float*)d_in[3];
    const float* Wo = (const float*)d_in[4];
    const float* qw = (const float*)d_in[5];
    const float* kw = (const float*)d_in[6];
    float* out = (float*)d_out;

    static __half *x16 = nullptr, *a16, *w1h, *w1l, *w2h, *w2l;
    if (!x16) {
        cudaGetSymbolAddress((void**)&x16, g_x16);
        cudaGetSymbolAddress((void**)&a16, g_a16);
        cudaGetSymbolAddress((void**)&w1h, g_w1h);
        cudaGetSymbolAddress((void**)&w1l, g_w1l);
        cudaGetSymbolAddress((void**)&w2h, g_w2h);
        cudaGetSymbolAddress((void**)&w2l, g_w2l);
        cudaFuncSetAttribute(attn_mma,
                             cudaFuncAttributeMaxDynamicSharedMemorySize, ATT_SMEM);
        cudaFuncSetAttribute(gemm_mma<0>,
                             cudaFuncAttributeMaxDynamicSharedMemorySize, SMEM_GEMM);
        cudaFuncSetAttribute(gemm_mma<1>,
                             cudaFuncAttributeMaxDynamicSharedMemorySize, SMEM_GEMM);
    }

    const int n4 = MROWS * GK / 4;
    cvt_half<<<(n4 + 255) / 256, 256>>>(x, x16, n4);
    xpose_qkv<<<(QKVC * GK + 255) / 256, 256>>>(Wq, Wk, Wv, w1h, w1l);
    xpose_wo<<<(DIM * GK + 255) / 256, 256>>>(Wo, w2h, w2l);

    gemm_mma<1><<<dim3(QKVC / 128, MROWS / 128), 256, SMEM_GEMM>>>(
        x16, w1h, w1l, nullptr, 0, qw, kw);

    attn_mma<<<dim3(NH, BTN), 256, ATT_SMEM>>>();

    gemm_mma<0><<<dim3(DIM / 128, MROWS / 128), 256, SMEM_GEMM>>>(
        a16, w2h, w2l, out, DIM, nullptr, nullptr);
}